// round 1
// baseline (speedup 1.0000x reference)
#include <cuda_runtime.h>
#include <math.h>

#define BB    4
#define TT    2048
#define DD    1024
#define EE    8
#define FF    1024
#define NTOK  (BB*TT)          // 8192 tokens
#define NASG  (NTOK*2)         // 16384 assignments (top_k = 2)
#define MAXA  (NASG + EE*64)   // padded assignment capacity (segments aligned to 64)
#define ROW_TILES (MAXA/64)    // 264

// ---------------- scratch (static device globals; no runtime allocation) ----
__device__ int   g_counts[EE];
__device__ int   g_cursor[EE];
__device__ int   g_offsets[EE+1];
__device__ int   g_eidx[NASG];
__device__ float g_ew[NASG];
__device__ int   g_token_of[MAXA];
__device__ float g_weight_of[MAXA];
__device__ int   g_assign_pos[NASG];
__device__ float g_h[(size_t)MAXA * FF];   // ~69 MB
__device__ float g_y[(size_t)MAXA * DD];   // ~69 MB

// ---------------- init -------------------------------------------------------
__global__ void init_kernel() {
    int i = blockIdx.x * blockDim.x + threadIdx.x;
    if (i < EE) { g_counts[i] = 0; g_cursor[i] = 0; }
    if (i < MAXA) { g_token_of[i] = -1; g_weight_of[i] = 0.f; }
}

// ---------------- router: logits -> softmax -> top2 -> renorm softmax -------
__global__ void router_kernel(const float* __restrict__ x,
                              const float* __restrict__ wr) {
    __shared__ float s_wr[DD * EE];  // 32 KB
    int tid = threadIdx.x;
    for (int i = tid; i < DD * EE / 4; i += blockDim.x)
        ((float4*)s_wr)[i] = ((const float4*)wr)[i];
    __syncthreads();

    int warp = tid >> 5, lane = tid & 31;
    int t = blockIdx.x * 8 + warp;
    const float* xr = x + (size_t)t * DD;

    float acc[EE];
#pragma unroll
    for (int e = 0; e < EE; e++) acc[e] = 0.f;

#pragma unroll
    for (int i = 0; i < 8; i++) {
        int d0 = i * 128 + lane * 4;
        float4 xv = *(const float4*)(xr + d0);
        float xa[4] = { xv.x, xv.y, xv.z, xv.w };
#pragma unroll
        for (int j = 0; j < 4; j++) {
            const float4* wp = (const float4*)(s_wr + (size_t)(d0 + j) * EE);
            float4 w0 = wp[0], w1 = wp[1];
            acc[0] += xa[j] * w0.x;  acc[1] += xa[j] * w0.y;
            acc[2] += xa[j] * w0.z;  acc[3] += xa[j] * w0.w;
            acc[4] += xa[j] * w1.x;  acc[5] += xa[j] * w1.y;
            acc[6] += xa[j] * w1.z;  acc[7] += xa[j] * w1.w;
        }
    }
#pragma unroll
    for (int off = 16; off > 0; off >>= 1)
#pragma unroll
        for (int e = 0; e < EE; e++)
            acc[e] += __shfl_xor_sync(0xffffffffu, acc[e], off);

    if (lane == 0) {
        float m = acc[0];
#pragma unroll
        for (int e = 1; e < EE; e++) m = fmaxf(m, acc[e]);
        float p[EE], s = 0.f;
#pragma unroll
        for (int e = 0; e < EE; e++) { p[e] = expf(acc[e] - m); s += p[e]; }
        float inv = 1.f / s;
#pragma unroll
        for (int e = 0; e < EE; e++) p[e] *= inv;

        int be = 0; float b = p[0];
#pragma unroll
        for (int e = 1; e < EE; e++) if (p[e] > b) { b = p[e]; be = e; }
        int be2 = -1; float b2 = -1.f;
#pragma unroll
        for (int e = 0; e < EE; e++)
            if (e != be && p[e] > b2) { b2 = p[e]; be2 = e; }

        // second softmax over the two selected probabilities (b >= b2)
        float w0 = 1.f / (1.f + expf(b2 - b));
        float w1 = 1.f - w0;

        g_eidx[2*t]   = be;   g_ew[2*t]   = w0;
        g_eidx[2*t+1] = be2;  g_ew[2*t+1] = w1;
        atomicAdd(&g_counts[be], 1);
        atomicAdd(&g_counts[be2], 1);
    }
}

// ---------------- offsets (padded to 64) -------------------------------------
__global__ void offsets_kernel() {
    int off = 0;
#pragma unroll
    for (int e = 0; e < EE; e++) {
        g_offsets[e] = off;
        off += (g_counts[e] + 63) & ~63;
    }
    g_offsets[EE] = off;
}

// ---------------- scatter assignments into expert segments -------------------
__global__ void scatter_kernel() {
    int i = blockIdx.x * blockDim.x + threadIdx.x;
    if (i >= NASG) return;
    int e = g_eidx[i];
    int pos = atomicAdd(&g_cursor[e], 1);
    int a = g_offsets[e] + pos;
    g_token_of[a] = i >> 1;
    g_weight_of[a] = g_ew[i];
    g_assign_pos[i] = a;
}

// ---------------- ff1: h = w * silu(x.Wg) * (x.Wu), grouped per expert -------
// BM=64, BN=64, BK=16, 256 threads, 4x4 micro-tile per thread, two B matrices.
__global__ void __launch_bounds__(256)
ff1_kernel(const float* __restrict__ x,
           const float* __restrict__ Wg,
           const float* __restrict__ Wu) {
    int m0 = blockIdx.y * 64;
    if (m0 >= g_offsets[EE]) return;
    int e = 0;
#pragma unroll
    for (int i = 0; i < EE; i++) if (m0 >= g_offsets[i+1]) e = i + 1;

    const float* wg = Wg + (size_t)e * DD * FF;
    const float* wu = Wu + (size_t)e * DD * FF;
    int n0 = blockIdx.x * 64;

    __shared__ float As[16][64];
    __shared__ float Bg[16][64];
    __shared__ float Bu[16][64];

    int tid = threadIdx.x;
    int tx = tid & 15, ty = tid >> 4;

    float accG[4][4], accU[4][4];
#pragma unroll
    for (int i = 0; i < 4; i++)
#pragma unroll
        for (int j = 0; j < 4; j++) { accG[i][j] = 0.f; accU[i][j] = 0.f; }

    int arow = tid >> 2;          // 0..63
    int ac   = (tid & 3) * 4;     // 0,4,8,12
    int tok  = g_token_of[m0 + arow];
    bool avalid = tok >= 0;
    const float* ap = x + (size_t)(avalid ? tok : 0) * DD + ac;

    int brow = tid >> 4;          // 0..15
    int bc   = (tid & 15) * 4;    // 0..60
    const float* gp = wg + (size_t)brow * FF + n0 + bc;
    const float* up = wu + (size_t)brow * FF + n0 + bc;

    for (int kt = 0; kt < DD; kt += 16) {
        float4 av = avalid ? *(const float4*)(ap + kt) : make_float4(0.f,0.f,0.f,0.f);
        float4 gv = *(const float4*)(gp + (size_t)kt * FF);
        float4 uv = *(const float4*)(up + (size_t)kt * FF);
        __syncthreads();
        As[ac+0][arow] = av.x; As[ac+1][arow] = av.y;
        As[ac+2][arow] = av.z; As[ac+3][arow] = av.w;
        *(float4*)&Bg[brow][bc] = gv;
        *(float4*)&Bu[brow][bc] = uv;
        __syncthreads();
#pragma unroll
        for (int k = 0; k < 16; k++) {
            float4 a4 = *(const float4*)&As[k][ty*4];
            float4 g4 = *(const float4*)&Bg[k][tx*4];
            float4 u4 = *(const float4*)&Bu[k][tx*4];
            float a[4]  = { a4.x, a4.y, a4.z, a4.w };
            float bg[4] = { g4.x, g4.y, g4.z, g4.w };
            float bu[4] = { u4.x, u4.y, u4.z, u4.w };
#pragma unroll
            for (int i = 0; i < 4; i++)
#pragma unroll
                for (int j = 0; j < 4; j++) {
                    accG[i][j] += a[i] * bg[j];
                    accU[i][j] += a[i] * bu[j];
                }
        }
    }

#pragma unroll
    for (int i = 0; i < 4; i++) {
        int m = m0 + ty * 4 + i;
        float w = g_weight_of[m];      // 0 on padded rows
        float4 hv;
        float* hh = (float*)&hv;
#pragma unroll
        for (int j = 0; j < 4; j++) {
            float g = accG[i][j], u = accU[i][j];
            float s = g / (1.f + expf(-g));   // silu
            hh[j] = w * s * u;
        }
        *(float4*)(g_h + (size_t)m * FF + n0 + tx * 4) = hv;
    }
}

// ---------------- ff2: y = h . Wd, grouped per expert ------------------------
__global__ void __launch_bounds__(256)
ff2_kernel(const float* __restrict__ Wd) {
    int m0 = blockIdx.y * 64;
    if (m0 >= g_offsets[EE]) return;
    int e = 0;
#pragma unroll
    for (int i = 0; i < EE; i++) if (m0 >= g_offsets[i+1]) e = i + 1;

    const float* wd = Wd + (size_t)e * FF * DD;
    int n0 = blockIdx.x * 64;

    __shared__ float As[16][64];
    __shared__ float Bs[16][64];

    int tid = threadIdx.x;
    int tx = tid & 15, ty = tid >> 4;

    float acc[4][4];
#pragma unroll
    for (int i = 0; i < 4; i++)
#pragma unroll
        for (int j = 0; j < 4; j++) acc[i][j] = 0.f;

    int arow = tid >> 2;
    int ac   = (tid & 3) * 4;
    const float* ap = g_h + (size_t)(m0 + arow) * FF + ac;

    int brow = tid >> 4;
    int bc   = (tid & 15) * 4;
    const float* bp = wd + (size_t)brow * DD + n0 + bc;

    for (int kt = 0; kt < FF; kt += 16) {
        float4 av = *(const float4*)(ap + kt);
        float4 bv = *(const float4*)(bp + (size_t)kt * DD);
        __syncthreads();
        As[ac+0][arow] = av.x; As[ac+1][arow] = av.y;
        As[ac+2][arow] = av.z; As[ac+3][arow] = av.w;
        *(float4*)&Bs[brow][bc] = bv;
        __syncthreads();
#pragma unroll
        for (int k = 0; k < 16; k++) {
            float4 a4 = *(const float4*)&As[k][ty*4];
            float4 b4 = *(const float4*)&Bs[k][tx*4];
            float a[4] = { a4.x, a4.y, a4.z, a4.w };
            float b[4] = { b4.x, b4.y, b4.z, b4.w };
#pragma unroll
            for (int i = 0; i < 4; i++)
#pragma unroll
                for (int j = 0; j < 4; j++)
                    acc[i][j] += a[i] * b[j];
        }
    }

#pragma unroll
    for (int i = 0; i < 4; i++) {
        int m = m0 + ty * 4 + i;
        float4 yv = make_float4(acc[i][0], acc[i][1], acc[i][2], acc[i][3]);
        *(float4*)(g_y + (size_t)m * DD + n0 + tx * 4) = yv;
    }
}

// ---------------- combine: out[t] = y[a0] + y[a1] ----------------------------
__global__ void combine_kernel(float* __restrict__ out) {
    int t = blockIdx.x;
    int a0 = g_assign_pos[2*t];
    int a1 = g_assign_pos[2*t+1];
    const float4* y0 = (const float4*)(g_y + (size_t)a0 * DD);
    const float4* y1 = (const float4*)(g_y + (size_t)a1 * DD);
    float4* o = (float4*)(out + (size_t)t * DD);
    int j = threadIdx.x;  // 256 = DD/4
    float4 v0 = y0[j], v1 = y1[j];
    o[j] = make_float4(v0.x + v1.x, v0.y + v1.y, v0.z + v1.z, v0.w + v1.w);
}

// ---------------- launch ------------------------------------------------------
extern "C" void kernel_launch(void* const* d_in, const int* in_sizes, int n_in,
                              void* d_out, int out_size) {
    const float* x  = (const float*)d_in[0];
    const float* wr = (const float*)d_in[1];
    const float* wg = (const float*)d_in[2];
    const float* wu = (const float*)d_in[3];
    const float* wd = (const float*)d_in[4];
    // d_in[5] = top_k (fixed at 2 for this problem)
    float* out = (float*)d_out;

    init_kernel<<<(MAXA + 255) / 256, 256>>>();
    router_kernel<<<NTOK / 8, 256>>>(x, wr);
    offsets_kernel<<<1, 1>>>();
    scatter_kernel<<<(NASG + 255) / 256, 256>>>();

    dim3 g1(FF / 64, ROW_TILES);
    ff1_kernel<<<g1, 256>>>(x, wg, wu);

    dim3 g2(DD / 64, ROW_TILES);
    ff2_kernel<<<g2, 256>>>(wd);

    combine_kernel<<<NTOK, 256>>>(out);
}

// round 3
// speedup vs baseline: 2.8198x; 2.8198x over previous
#include <cuda_runtime.h>
#include <math.h>
#include <stdint.h>

#define BB 4
#define TT 2048
#define DD 1024
#define EE 8
#define FF 1024
#define NTOK (BB*TT)           // 8192
#define NASG (NTOK*2)          // 16384
#define MAXA (NASG + EE*128)   // 17408
#define MTILES (MAXA/128)      // 136

// ---------------- scratch ----------------
__device__ int   g_counts[EE];
__device__ int   g_cursor[EE];
__device__ int   g_offsets[EE+1];
__device__ int   g_eidx[NASG];
__device__ float g_ew[NASG];
__device__ int   g_token_of[MAXA];
__device__ float g_weight_of[MAXA];
__device__ int   g_assign_pos[NASG];

__device__ float g_xr [(size_t)NTOK*DD];       // tf32-rounded x
__device__ float g_wgr[(size_t)EE*DD*FF];      // tf32-rounded weights
__device__ float g_wur[(size_t)EE*DD*FF];
__device__ float g_wdr[(size_t)EE*FF*DD];
__device__ float g_h  [(size_t)MAXA*FF];       // ff1 output (tf32-rounded)
__device__ float g_y  [(size_t)MAXA*DD];       // ff2 output

// ---------------- PTX helpers ----------------
__device__ __forceinline__ uint32_t s2u(const void* p) {
    uint32_t a;
    asm("{ .reg .u64 t; cvta.to.shared.u64 t, %1; cvt.u32.u64 %0, t; }" : "=r"(a) : "l"(p));
    return a;
}
#define CP16(dst, src) \
    asm volatile("cp.async.cg.shared.global [%0], [%1], 16;" :: "r"(dst), "l"(src) : "memory")
#define CP_COMMIT() asm volatile("cp.async.commit_group;" ::: "memory")
#define CP_WAIT(N)  asm volatile("cp.async.wait_group %0;" :: "n"(N) : "memory")

__device__ __forceinline__ float tf32r(float v) {
    uint32_t u;
    asm("cvt.rna.tf32.f32 %0, %1;" : "=r"(u) : "f"(v));
    return __uint_as_float(u);
}

// mma.sync m16n8k8 tf32: D += A*B
#define MMA_TF32(d, a, b0, b1) \
    asm volatile("mma.sync.aligned.m16n8k8.row.col.f32.tf32.tf32.f32 " \
        "{%0,%1,%2,%3}, {%4,%5,%6,%7}, {%8,%9}, {%0,%1,%2,%3};" \
        : "+f"((d)[0]), "+f"((d)[1]), "+f"((d)[2]), "+f"((d)[3]) \
        : "r"(__float_as_uint((a)[0])), "r"(__float_as_uint((a)[1])), \
          "r"(__float_as_uint((a)[2])), "r"(__float_as_uint((a)[3])), \
          "r"(__float_as_uint(b0)),    "r"(__float_as_uint(b1)))

// ---------------- init ----------------
__global__ void init_kernel() {
    int i = blockIdx.x * blockDim.x + threadIdx.x;
    if (i < EE) { g_counts[i] = 0; g_cursor[i] = 0; }
    if (i < MAXA) { g_token_of[i] = -1; g_weight_of[i] = 0.f; }
}

// ---------------- tf32 pre-round ----------------
__global__ void roundcvt(const float* __restrict__ src, float* __restrict__ dst, int n4) {
    int i = blockIdx.x * blockDim.x + threadIdx.x;
    if (i >= n4) return;
    float4 v = ((const float4*)src)[i];
    v.x = tf32r(v.x); v.y = tf32r(v.y); v.z = tf32r(v.z); v.w = tf32r(v.w);
    ((float4*)dst)[i] = v;
}

// ---------------- router ----------------
__global__ void router_kernel(const float* __restrict__ x,
                              const float* __restrict__ wr) {
    __shared__ float s_wr[DD * EE];
    int tid = threadIdx.x;
    for (int i = tid; i < DD * EE / 4; i += blockDim.x)
        ((float4*)s_wr)[i] = ((const float4*)wr)[i];
    __syncthreads();

    int warp = tid >> 5, lane = tid & 31;
    int t = blockIdx.x * 8 + warp;
    const float* xr = x + (size_t)t * DD;

    float acc[EE];
#pragma unroll
    for (int e = 0; e < EE; e++) acc[e] = 0.f;
#pragma unroll
    for (int i = 0; i < 8; i++) {
        int d0 = i * 128 + lane * 4;
        float4 xv = *(const float4*)(xr + d0);
        float xa[4] = { xv.x, xv.y, xv.z, xv.w };
#pragma unroll
        for (int j = 0; j < 4; j++) {
            const float4* wp = (const float4*)(s_wr + (size_t)(d0 + j) * EE);
            float4 w0 = wp[0], w1 = wp[1];
            acc[0] += xa[j] * w0.x;  acc[1] += xa[j] * w0.y;
            acc[2] += xa[j] * w0.z;  acc[3] += xa[j] * w0.w;
            acc[4] += xa[j] * w1.x;  acc[5] += xa[j] * w1.y;
            acc[6] += xa[j] * w1.z;  acc[7] += xa[j] * w1.w;
        }
    }
#pragma unroll
    for (int off = 16; off > 0; off >>= 1)
#pragma unroll
        for (int e = 0; e < EE; e++)
            acc[e] += __shfl_xor_sync(0xffffffffu, acc[e], off);

    if (lane == 0) {
        float m = acc[0];
#pragma unroll
        for (int e = 1; e < EE; e++) m = fmaxf(m, acc[e]);
        float p[EE], s = 0.f;
#pragma unroll
        for (int e = 0; e < EE; e++) { p[e] = expf(acc[e] - m); s += p[e]; }
        float inv = 1.f / s;
#pragma unroll
        for (int e = 0; e < EE; e++) p[e] *= inv;

        int be = 0; float b = p[0];
#pragma unroll
        for (int e = 1; e < EE; e++) if (p[e] > b) { b = p[e]; be = e; }
        int be2 = -1; float b2 = -1.f;
#pragma unroll
        for (int e = 0; e < EE; e++)
            if (e != be && p[e] > b2) { b2 = p[e]; be2 = e; }

        float w0 = 1.f / (1.f + expf(b2 - b));
        float w1 = 1.f - w0;

        g_eidx[2*t]   = be;   g_ew[2*t]   = w0;
        g_eidx[2*t+1] = be2;  g_ew[2*t+1] = w1;
        atomicAdd(&g_counts[be], 1);
        atomicAdd(&g_counts[be2], 1);
    }
}

__global__ void offsets_kernel() {
    int off = 0;
#pragma unroll
    for (int e = 0; e < EE; e++) {
        g_offsets[e] = off;
        off += (g_counts[e] + 127) & ~127;
    }
    g_offsets[EE] = off;
}

__global__ void scatter_kernel() {
    int i = blockIdx.x * blockDim.x + threadIdx.x;
    if (i >= NASG) return;
    int e = g_eidx[i];
    int pos = atomicAdd(&g_cursor[e], 1);
    int a = g_offsets[e] + pos;
    g_token_of[a] = i >> 1;
    g_weight_of[a] = g_ew[i];
    g_assign_pos[i] = a;
}

// ======================= ff1 : gate+up grouped GEMM (tf32 mma) ===============
// BM=128, BN=64 (two B matrices), BK=32, 3-stage cp.async, 256 threads.
// smem per stage (bytes): A 128*144=18432, Bg 32*288=9216, Bu 9216 -> 36864
#define F1_STAGE 36864
#define F1_AS 36   // A row stride (floats)
#define F1_BS 72   // B row stride (floats)

__global__ void __launch_bounds__(256, 2)
ff1_tc(const float* __restrict__ xr,
       const float* __restrict__ wgr,
       const float* __restrict__ wur) {
    extern __shared__ char smem[];
    int m0 = blockIdx.y * 128;
    if (m0 >= g_offsets[EE]) return;
    int e = 0;
#pragma unroll
    for (int i = 0; i < EE; i++) if (m0 >= g_offsets[i+1]) e = i + 1;
    int n0 = blockIdx.x * 64;

    int tid = threadIdx.x, wid = tid >> 5, lane = tid & 31;
    int wm = wid & 3, wn = wid >> 2;
    int ly = lane >> 2, lx = lane & 3;
    uint32_t sb = s2u(smem);

    // -- loader setup --
    int ar = tid >> 1, ah = tid & 1;
    int tok = g_token_of[m0 + ar]; if (tok < 0) tok = 0;
    const char* aSrc = (const char*)(xr + (size_t)tok * DD) + ah * 64;
    uint32_t aDst = (uint32_t)(ar * 144 + ah * 64);
    const char* gBase = (const char*)(wgr + ((size_t)e << 20) + n0);
    const char* uBase = (const char*)(wur + ((size_t)e << 20) + n0);
    int bk0 = tid >> 4, bc0 = (tid & 15) * 16;          // chunk 0
    int bk1 = (tid + 256) >> 4, bc1 = bc0;              // chunk 1 (tid&15 same)

    float accG[2][4][4], accU[2][4][4];
#pragma unroll
    for (int a = 0; a < 2; a++)
#pragma unroll
        for (int b = 0; b < 4; b++)
#pragma unroll
            for (int c = 0; c < 4; c++) { accG[a][b][c] = 0.f; accU[a][b][c] = 0.f; }

#define F1_LOAD(kt, slot) do { \
    uint32_t s_ = sb + (slot) * F1_STAGE; \
    const char* as_ = aSrc + (kt) * 128; \
    CP16(s_ + aDst,      as_);      CP16(s_ + aDst + 16, as_ + 16); \
    CP16(s_ + aDst + 32, as_ + 32); CP16(s_ + aDst + 48, as_ + 48); \
    size_t go0_ = (size_t)((kt) * 32 + bk0) * 4096 + bc0; \
    size_t go1_ = (size_t)((kt) * 32 + bk1) * 4096 + bc1; \
    uint32_t bo0_ = s_ + 18432 + bk0 * 288 + bc0; \
    uint32_t bo1_ = s_ + 18432 + bk1 * 288 + bc1; \
    CP16(bo0_,        gBase + go0_);  CP16(bo1_,        gBase + go1_); \
    CP16(bo0_ + 9216, uBase + go0_);  CP16(bo1_ + 9216, uBase + go1_); \
    CP_COMMIT(); \
} while (0)

    F1_LOAD(0, 0);
    F1_LOAD(1, 1);

    const int NIT = DD / 32;   // 32
#pragma unroll 1
    for (int kt = 0; kt < NIT; kt++) {
        if (kt == NIT - 1) { CP_WAIT(0); } else { CP_WAIT(1); }
        __syncthreads();
        if (kt + 2 < NIT) F1_LOAD(kt + 2, (kt + 2) % 3);

        const float* Sf = (const float*)(smem + (kt % 3) * F1_STAGE);
        const float* As = Sf;
        const float* Bg = Sf + 4608;
        const float* Bu = Sf + 6912;

#pragma unroll
        for (int ks = 0; ks < 4; ks++) {
            int ko = ks * 8;
            float a[2][4];
#pragma unroll
            for (int mt = 0; mt < 2; mt++) {
                int m = wm * 32 + mt * 16;
                a[mt][0] = As[(m + ly)     * F1_AS + ko + lx];
                a[mt][1] = As[(m + ly + 8) * F1_AS + ko + lx];
                a[mt][2] = As[(m + ly)     * F1_AS + ko + lx + 4];
                a[mt][3] = As[(m + ly + 8) * F1_AS + ko + lx + 4];
            }
#pragma unroll
            for (int nt = 0; nt < 4; nt++) {
                int n = wn * 32 + nt * 8 + ly;
                float bg0 = Bg[(ko + lx)     * F1_BS + n];
                float bg1 = Bg[(ko + lx + 4) * F1_BS + n];
                float bu0 = Bu[(ko + lx)     * F1_BS + n];
                float bu1 = Bu[(ko + lx + 4) * F1_BS + n];
#pragma unroll
                for (int mt = 0; mt < 2; mt++) {
                    MMA_TF32(accG[mt][nt], a[mt], bg0, bg1);
                    MMA_TF32(accU[mt][nt], a[mt], bu0, bu1);
                }
            }
        }
    }

    // epilogue: h = w * silu(g) * u, tf32-rounded
#pragma unroll
    for (int mt = 0; mt < 2; mt++) {
        int r0 = m0 + wm * 32 + mt * 16 + ly;
        float w0 = g_weight_of[r0], w1 = g_weight_of[r0 + 8];
#pragma unroll
        for (int nt = 0; nt < 4; nt++) {
            int c = n0 + wn * 32 + nt * 8 + 2 * lx;
            float* G = accG[mt][nt];
            float* U = accU[mt][nt];
            float h0 = w0 * (G[0] / (1.f + __expf(-G[0]))) * U[0];
            float h1 = w0 * (G[1] / (1.f + __expf(-G[1]))) * U[1];
            float h2 = w1 * (G[2] / (1.f + __expf(-G[2]))) * U[2];
            float h3 = w1 * (G[3] / (1.f + __expf(-G[3]))) * U[3];
            *(float2*)(g_h + (size_t)r0 * FF + c)       = make_float2(tf32r(h0), tf32r(h1));
            *(float2*)(g_h + (size_t)(r0 + 8) * FF + c) = make_float2(tf32r(h2), tf32r(h3));
        }
    }
}

// ======================= ff2 : down grouped GEMM (tf32 mma) ==================
// BM=128, BN=128, BK=32, 3-stage. smem/stage: A 18432 + B 32*544=17408 -> 35840
#define F2_STAGE 35840
#define F2_BS 136

__global__ void __launch_bounds__(256, 2)
ff2_tc(const float* __restrict__ wdr) {
    extern __shared__ char smem[];
    int m0 = blockIdx.y * 128;
    if (m0 >= g_offsets[EE]) return;
    int e = 0;
#pragma unroll
    for (int i = 0; i < EE; i++) if (m0 >= g_offsets[i+1]) e = i + 1;
    int n0 = blockIdx.x * 128;

    int tid = threadIdx.x, wid = tid >> 5, lane = tid & 31;
    int wm = wid & 3, wn = wid >> 2;
    int ly = lane >> 2, lx = lane & 3;
    uint32_t sb = s2u(smem);

    int ar = tid >> 1, ah = tid & 1;
    const char* aSrc = (const char*)(g_h + (size_t)(m0 + ar) * FF) + ah * 64;
    uint32_t aDst = (uint32_t)(ar * 144 + ah * 64);
    const char* bBase = (const char*)(wdr + ((size_t)e << 20) + n0);

    float acc[2][8][4];
#pragma unroll
    for (int a = 0; a < 2; a++)
#pragma unroll
        for (int b = 0; b < 8; b++)
#pragma unroll
            for (int c = 0; c < 4; c++) acc[a][b][c] = 0.f;

#define F2_LOAD(kt, slot) do { \
    uint32_t s_ = sb + (slot) * F2_STAGE; \
    const char* as_ = aSrc + (kt) * 128; \
    CP16(s_ + aDst,      as_);      CP16(s_ + aDst + 16, as_ + 16); \
    CP16(s_ + aDst + 32, as_ + 32); CP16(s_ + aDst + 48, as_ + 48); \
    _Pragma("unroll") \
    for (int q_ = 0; q_ < 4; q_++) { \
        int id_ = tid + q_ * 256; \
        int k_ = id_ >> 5, c_ = (id_ & 31) * 16; \
        CP16(s_ + 18432 + k_ * 544 + c_, bBase + (size_t)((kt) * 32 + k_) * 4096 + c_); \
    } \
    CP_COMMIT(); \
} while (0)

    F2_LOAD(0, 0);
    F2_LOAD(1, 1);

    const int NIT = FF / 32;
#pragma unroll 1
    for (int kt = 0; kt < NIT; kt++) {
        if (kt == NIT - 1) { CP_WAIT(0); } else { CP_WAIT(1); }
        __syncthreads();
        if (kt + 2 < NIT) F2_LOAD(kt + 2, (kt + 2) % 3);

        const float* Sf = (const float*)(smem + (kt % 3) * F2_STAGE);
        const float* As = Sf;
        const float* Bs = Sf + 4608;

#pragma unroll
        for (int ks = 0; ks < 4; ks++) {
            int ko = ks * 8;
            float a[2][4];
#pragma unroll
            for (int mt = 0; mt < 2; mt++) {
                int m = wm * 32 + mt * 16;
                a[mt][0] = As[(m + ly)     * F1_AS + ko + lx];
                a[mt][1] = As[(m + ly + 8) * F1_AS + ko + lx];
                a[mt][2] = As[(m + ly)     * F1_AS + ko + lx + 4];
                a[mt][3] = As[(m + ly + 8) * F1_AS + ko + lx + 4];
            }
#pragma unroll
            for (int nt = 0; nt < 8; nt++) {
                int n = wn * 64 + nt * 8 + ly;
                float b0 = Bs[(ko + lx)     * F2_BS + n];
                float b1 = Bs[(ko + lx + 4) * F2_BS + n];
#pragma unroll
                for (int mt = 0; mt < 2; mt++)
                    MMA_TF32(acc[mt][nt], a[mt], b0, b1);
            }
        }
    }

#pragma unroll
    for (int mt = 0; mt < 2; mt++) {
        int r0 = m0 + wm * 32 + mt * 16 + ly;
#pragma unroll
        for (int nt = 0; nt < 8; nt++) {
            int c = n0 + wn * 64 + nt * 8 + 2 * lx;
            float* A = acc[mt][nt];
            *(float2*)(g_y + (size_t)r0 * DD + c)       = make_float2(A[0], A[1]);
            *(float2*)(g_y + (size_t)(r0 + 8) * DD + c) = make_float2(A[2], A[3]);
        }
    }
}

// ---------------- combine ----------------
__global__ void combine_kernel(float* __restrict__ out) {
    int t = blockIdx.x;
    int a0 = g_assign_pos[2*t];
    int a1 = g_assign_pos[2*t+1];
    const float4* y0 = (const float4*)(g_y + (size_t)a0 * DD);
    const float4* y1 = (const float4*)(g_y + (size_t)a1 * DD);
    float4* o = (float4*)(out + (size_t)t * DD);
    int j = threadIdx.x;
    float4 v0 = y0[j], v1 = y1[j];
    o[j] = make_float4(v0.x + v1.x, v0.y + v1.y, v0.z + v1.z, v0.w + v1.w);
}

// ---------------- launch ----------------
extern "C" void kernel_launch(void* const* d_in, const int* in_sizes, int n_in,
                              void* d_out, int out_size) {
    const float* x  = (const float*)d_in[0];
    const float* wr = (const float*)d_in[1];
    const float* wg = (const float*)d_in[2];
    const float* wu = (const float*)d_in[3];
    const float* wd = (const float*)d_in[4];
    float* out = (float*)d_out;

    cudaFuncSetAttribute(ff1_tc, cudaFuncAttributeMaxDynamicSharedMemorySize, 3 * F1_STAGE);
    cudaFuncSetAttribute(ff2_tc, cudaFuncAttributeMaxDynamicSharedMemorySize, 3 * F2_STAGE);

    init_kernel<<<(MAXA + 255) / 256, 256>>>();
    router_kernel<<<NTOK / 8, 256>>>(x, wr);
    offsets_kernel<<<1, 1>>>();
    scatter_kernel<<<(NASG + 255) / 256, 256>>>();

    float* xr_p;  cudaGetSymbolAddress((void**)&xr_p,  g_xr);
    float* wgr_p; cudaGetSymbolAddress((void**)&wgr_p, g_wgr);
    float* wur_p; cudaGetSymbolAddress((void**)&wur_p, g_wur);
    float* wdr_p; cudaGetSymbolAddress((void**)&wdr_p, g_wdr);

    roundcvt<<<(NTOK*DD/4 + 255)/256, 256>>>(x,  xr_p,  NTOK*DD/4);
    roundcvt<<<(EE*DD*FF/4 + 255)/256, 256>>>(wg, wgr_p, EE*DD*FF/4);
    roundcvt<<<(EE*DD*FF/4 + 255)/256, 256>>>(wu, wur_p, EE*DD*FF/4);
    roundcvt<<<(EE*FF*DD/4 + 255)/256, 256>>>(wd, wdr_p, EE*FF*DD/4);

    {
        dim3 g(FF / 64, MTILES);
        ff1_tc<<<g, 256, 3 * F1_STAGE>>>(xr_p, wgr_p, wur_p);
    }
    {
        dim3 g(DD / 128, MTILES);
        ff2_tc<<<g, 256, 3 * F2_STAGE>>>(wdr_p);
    }
    combine_kernel<<<NTOK, 256>>>(out);
}

// round 4
// speedup vs baseline: 5.1903x; 1.8407x over previous
#include <cuda_runtime.h>
#include <cuda_fp16.h>
#include <math.h>
#include <stdint.h>

#define BB 4
#define TT 2048
#define DD 1024
#define EE 8
#define FF 1024
#define NTOK (BB*TT)           // 8192
#define NASG (NTOK*2)          // 16384
#define MAXA (NASG + EE*128)   // 17408
#define MTILES (MAXA/128)      // 136

// ---------------- scratch ----------------
__device__ int   g_counts[EE];
__device__ int   g_cursor[EE];
__device__ int   g_offsets[EE+1];
__device__ int   g_eidx[NASG];
__device__ float g_ew[NASG];
__device__ int   g_token_of[MAXA];
__device__ float g_weight_of[MAXA];
__device__ int   g_assign_pos[NASG];

__device__ __half g_xh [(size_t)NTOK*DD];
__device__ __half g_wgh[(size_t)EE*DD*FF];
__device__ __half g_wuh[(size_t)EE*DD*FF];
__device__ __half g_wdh[(size_t)EE*FF*DD];
__device__ __half g_h  [(size_t)MAXA*FF];
__device__ float  g_y  [(size_t)MAXA*DD];

// ---------------- PTX helpers ----------------
__device__ __forceinline__ uint32_t s2u(const void* p) {
    uint32_t a;
    asm("{ .reg .u64 t; cvta.to.shared.u64 t, %1; cvt.u32.u64 %0, t; }" : "=r"(a) : "l"(p));
    return a;
}
#define CP16(dst, src) \
    asm volatile("cp.async.cg.shared.global [%0], [%1], 16;" :: "r"(dst), "l"(src) : "memory")
#define CP_COMMIT() asm volatile("cp.async.commit_group;" ::: "memory")
#define CP_WAIT(N)  asm volatile("cp.async.wait_group %0;" :: "n"(N) : "memory")

#define LDSM4(r0, r1, r2, r3, a) \
    asm volatile("ldmatrix.sync.aligned.m8n8.x4.shared.b16 {%0,%1,%2,%3}, [%4];" \
        : "=r"(r0), "=r"(r1), "=r"(r2), "=r"(r3) : "r"(a))
#define LDSM4T(r0, r1, r2, r3, a) \
    asm volatile("ldmatrix.sync.aligned.m8n8.x4.trans.shared.b16 {%0,%1,%2,%3}, [%4];" \
        : "=r"(r0), "=r"(r1), "=r"(r2), "=r"(r3) : "r"(a))

// mma m16n8k16 fp16 in, fp32 acc
#define MMA_F16(d, a, b0, b1) \
    asm volatile("mma.sync.aligned.m16n8k16.row.col.f32.f16.f16.f32 " \
        "{%0,%1,%2,%3}, {%4,%5,%6,%7}, {%8,%9}, {%0,%1,%2,%3};" \
        : "+f"((d)[0]), "+f"((d)[1]), "+f"((d)[2]), "+f"((d)[3]) \
        : "r"((a)[0]), "r"((a)[1]), "r"((a)[2]), "r"((a)[3]), \
          "r"(b0), "r"(b1))

// ---------------- init ----------------
__global__ void init_kernel() {
    int i = blockIdx.x * blockDim.x + threadIdx.x;
    if (i < EE) { g_counts[i] = 0; g_cursor[i] = 0; }
    if (i < MAXA) { g_token_of[i] = -1; g_weight_of[i] = 0.f; }
}

// ---------------- fp32 -> fp16 convert ----------------
__global__ void cvt_half(const float* __restrict__ src, __half* __restrict__ dst, int n4) {
    int i = blockIdx.x * blockDim.x + threadIdx.x;
    if (i >= n4) return;
    float4 v = ((const float4*)src)[i];
    __half2 a = __floats2half2_rn(v.x, v.y);
    __half2 b = __floats2half2_rn(v.z, v.w);
    ((__half2*)dst)[2*i]   = a;
    ((__half2*)dst)[2*i+1] = b;
}

// ---------------- router ----------------
__global__ void router_kernel(const float* __restrict__ x,
                              const float* __restrict__ wr) {
    __shared__ float s_wr[DD * EE];
    int tid = threadIdx.x;
    for (int i = tid; i < DD * EE / 4; i += blockDim.x)
        ((float4*)s_wr)[i] = ((const float4*)wr)[i];
    __syncthreads();

    int warp = tid >> 5, lane = tid & 31;
    int t = blockIdx.x * 8 + warp;
    const float* xr = x + (size_t)t * DD;

    float acc[EE];
#pragma unroll
    for (int e = 0; e < EE; e++) acc[e] = 0.f;
#pragma unroll
    for (int i = 0; i < 8; i++) {
        int d0 = i * 128 + lane * 4;
        float4 xv = *(const float4*)(xr + d0);
        float xa[4] = { xv.x, xv.y, xv.z, xv.w };
#pragma unroll
        for (int j = 0; j < 4; j++) {
            const float4* wp = (const float4*)(s_wr + (size_t)(d0 + j) * EE);
            float4 w0 = wp[0], w1 = wp[1];
            acc[0] += xa[j] * w0.x;  acc[1] += xa[j] * w0.y;
            acc[2] += xa[j] * w0.z;  acc[3] += xa[j] * w0.w;
            acc[4] += xa[j] * w1.x;  acc[5] += xa[j] * w1.y;
            acc[6] += xa[j] * w1.z;  acc[7] += xa[j] * w1.w;
        }
    }
#pragma unroll
    for (int off = 16; off > 0; off >>= 1)
#pragma unroll
        for (int e = 0; e < EE; e++)
            acc[e] += __shfl_xor_sync(0xffffffffu, acc[e], off);

    if (lane == 0) {
        float m = acc[0];
#pragma unroll
        for (int e = 1; e < EE; e++) m = fmaxf(m, acc[e]);
        float p[EE], s = 0.f;
#pragma unroll
        for (int e = 0; e < EE; e++) { p[e] = expf(acc[e] - m); s += p[e]; }
        float inv = 1.f / s;
#pragma unroll
        for (int e = 0; e < EE; e++) p[e] *= inv;

        int be = 0; float b = p[0];
#pragma unroll
        for (int e = 1; e < EE; e++) if (p[e] > b) { b = p[e]; be = e; }
        int be2 = -1; float b2 = -1.f;
#pragma unroll
        for (int e = 0; e < EE; e++)
            if (e != be && p[e] > b2) { b2 = p[e]; be2 = e; }

        float w0 = 1.f / (1.f + expf(b2 - b));
        float w1 = 1.f - w0;

        g_eidx[2*t]   = be;   g_ew[2*t]   = w0;
        g_eidx[2*t+1] = be2;  g_ew[2*t+1] = w1;
        atomicAdd(&g_counts[be], 1);
        atomicAdd(&g_counts[be2], 1);
    }
}

__global__ void offsets_kernel() {
    int off = 0;
#pragma unroll
    for (int e = 0; e < EE; e++) {
        g_offsets[e] = off;
        off += (g_counts[e] + 127) & ~127;
    }
    g_offsets[EE] = off;
}

__global__ void scatter_kernel() {
    int i = blockIdx.x * blockDim.x + threadIdx.x;
    if (i >= NASG) return;
    int e = g_eidx[i];
    int pos = atomicAdd(&g_cursor[e], 1);
    int a = g_offsets[e] + pos;
    g_token_of[a] = i >> 1;
    g_weight_of[a] = g_ew[i];
    g_assign_pos[i] = a;
}

// ======================= ff1 : gate+up grouped GEMM (fp16 mma) ===============
// BM=128, BN=64 (two Bs), BK=32, 3 stages, 256 threads, warp tile 32x32.
// A stride 80 B (40 halves), B stride 144 B (72 halves). Stage = 19456 B.
#define F1_STAGE 19456
#define F1_BOFF  10240

__global__ void __launch_bounds__(256, 2)
ff1_tc(const __half* __restrict__ xh,
       const __half* __restrict__ wgh,
       const __half* __restrict__ wuh) {
    extern __shared__ char smem[];
    int m0 = blockIdx.y * 128;
    if (m0 >= g_offsets[EE]) return;
    int e = 0;
#pragma unroll
    for (int i = 0; i < EE; i++) if (m0 >= g_offsets[i+1]) e = i + 1;
    int n0 = blockIdx.x * 64;

    int tid = threadIdx.x, wid = tid >> 5, lane = tid & 31;
    int wm = wid & 3, wn = wid >> 2;
    int ly = lane >> 2, lx = lane & 3;
    uint32_t sb = s2u(smem);

    // loaders
    int ar = tid >> 1, ah = tid & 1;
    int tok = g_token_of[m0 + ar]; if (tok < 0) tok = 0;
    const char* aSrc = (const char*)(xh + (size_t)tok * DD) + ah * 32;
    uint32_t aDst = (uint32_t)(ar * 80 + ah * 32);
    const char* gBase = (const char*)(wgh + ((size_t)e << 20) + n0);
    const char* uBase = (const char*)(wuh + ((size_t)e << 20) + n0);
    // B: 512 chunks of 16B -> 2 per thread
    int id0 = tid, id1 = tid + 256;
    int brow0 = id0 >> 3, bc0 = (id0 & 7) * 16;
    int brow1 = id1 >> 3, bc1 = (id1 & 7) * 16;
    int bmat0 = brow0 >> 5, bk0 = brow0 & 31;
    int bmat1 = brow1 >> 5, bk1 = brow1 & 31;
    const char* bsrc0 = (bmat0 ? uBase : gBase) + bc0;
    const char* bsrc1 = (bmat1 ? uBase : gBase) + bc1;
    uint32_t bdst0 = (uint32_t)(F1_BOFF + bmat0 * 4608 + bk0 * 144 + bc0);
    uint32_t bdst1 = (uint32_t)(F1_BOFF + bmat1 * 4608 + bk1 * 144 + bc1);

    float accG[2][4][4], accU[2][4][4];
#pragma unroll
    for (int a = 0; a < 2; a++)
#pragma unroll
        for (int b = 0; b < 4; b++)
#pragma unroll
            for (int c = 0; c < 4; c++) { accG[a][b][c] = 0.f; accU[a][b][c] = 0.f; }

#define F1_LOAD(kt, slot) do { \
    uint32_t s_ = sb + (slot) * F1_STAGE; \
    const char* as_ = aSrc + (kt) * 64; \
    CP16(s_ + aDst, as_);  CP16(s_ + aDst + 16, as_ + 16); \
    CP16(s_ + bdst0, bsrc0 + (size_t)((kt) * 32 + bk0) * 2048); \
    CP16(s_ + bdst1, bsrc1 + (size_t)((kt) * 32 + bk1) * 2048); \
    CP_COMMIT(); \
} while (0)

    F1_LOAD(0, 0);
    F1_LOAD(1, 1);

    // ldmatrix lane addressing
    uint32_t l16 = (uint32_t)(lane & 15), lh = (uint32_t)(lane >> 4) * 16;

    const int NIT = DD / 32;
#pragma unroll 1
    for (int kt = 0; kt < NIT; kt++) {
        if (kt == NIT - 1) { CP_WAIT(0); } else { CP_WAIT(1); }
        __syncthreads();
        if (kt + 2 < NIT) F1_LOAD(kt + 2, (kt + 2) % 3);

        uint32_t stg = sb + (kt % 3) * F1_STAGE;
#pragma unroll
        for (int ks = 0; ks < 2; ks++) {
            uint32_t a_fr[2][4];
#pragma unroll
            for (int mt = 0; mt < 2; mt++) {
                uint32_t aa = stg + (wm * 32 + mt * 16 + l16) * 80 + ks * 32 + lh;
                LDSM4(a_fr[mt][0], a_fr[mt][1], a_fr[mt][2], a_fr[mt][3], aa);
            }
#pragma unroll
            for (int nt = 0; nt < 2; nt++) {
                uint32_t bg = stg + F1_BOFF + (ks * 16 + l16) * 144 +
                              (wn * 32 + nt * 16) * 2 + lh;
                uint32_t g0, g1, g2, g3, u0, u1, u2, u3;
                LDSM4T(g0, g1, g2, g3, bg);
                LDSM4T(u0, u1, u2, u3, bg + 4608);
#pragma unroll
                for (int mt = 0; mt < 2; mt++) {
                    MMA_F16(accG[mt][nt*2],   a_fr[mt], g0, g1);
                    MMA_F16(accG[mt][nt*2+1], a_fr[mt], g2, g3);
                    MMA_F16(accU[mt][nt*2],   a_fr[mt], u0, u1);
                    MMA_F16(accU[mt][nt*2+1], a_fr[mt], u2, u3);
                }
            }
        }
    }

    // epilogue: h = w * silu(g) * u -> fp16
#pragma unroll
    for (int mt = 0; mt < 2; mt++) {
        int r0 = m0 + wm * 32 + mt * 16 + ly;
        float w0 = g_weight_of[r0], w1 = g_weight_of[r0 + 8];
#pragma unroll
        for (int nt = 0; nt < 4; nt++) {
            int c = n0 + wn * 32 + nt * 8 + 2 * lx;
            float* G = accG[mt][nt];
            float* U = accU[mt][nt];
            float h0 = w0 * (G[0] / (1.f + __expf(-G[0]))) * U[0];
            float h1 = w0 * (G[1] / (1.f + __expf(-G[1]))) * U[1];
            float h2 = w1 * (G[2] / (1.f + __expf(-G[2]))) * U[2];
            float h3 = w1 * (G[3] / (1.f + __expf(-G[3]))) * U[3];
            *(__half2*)(g_h + (size_t)r0 * FF + c)       = __floats2half2_rn(h0, h1);
            *(__half2*)(g_h + (size_t)(r0 + 8) * FF + c) = __floats2half2_rn(h2, h3);
        }
    }
}

// ======================= ff2 : down grouped GEMM (fp16 mma) ==================
// BM=128, BN=128, BK=32, 3 stages, warp tile 32x64.
// A stride 80 B, B stride 272 B. Stage = 10240 + 8704 = 18944 B.
#define F2_STAGE 18944
#define F2_BOFF  10240

__global__ void __launch_bounds__(256, 2)
ff2_tc(const __half* __restrict__ wdh) {
    extern __shared__ char smem[];
    int m0 = blockIdx.y * 128;
    if (m0 >= g_offsets[EE]) return;
    int e = 0;
#pragma unroll
    for (int i = 0; i < EE; i++) if (m0 >= g_offsets[i+1]) e = i + 1;
    int n0 = blockIdx.x * 128;

    int tid = threadIdx.x, wid = tid >> 5, lane = tid & 31;
    int wm = wid & 3, wn = wid >> 2;
    int ly = lane >> 2, lx = lane & 3;
    uint32_t sb = s2u(smem);

    int ar = tid >> 1, ah = tid & 1;
    const char* aSrc = (const char*)(g_h + (size_t)(m0 + ar) * FF) + ah * 32;
    uint32_t aDst = (uint32_t)(ar * 80 + ah * 32);
    const char* bBase = (const char*)(wdh + ((size_t)e << 20) + n0);
    int id0 = tid, id1 = tid + 256;
    int bk0 = id0 >> 4, bc0 = (id0 & 15) * 16;
    int bk1 = id1 >> 4, bc1 = (id1 & 15) * 16;
    uint32_t bdst0 = (uint32_t)(F2_BOFF + bk0 * 272 + bc0);
    uint32_t bdst1 = (uint32_t)(F2_BOFF + bk1 * 272 + bc1);

    float acc[2][8][4];
#pragma unroll
    for (int a = 0; a < 2; a++)
#pragma unroll
        for (int b = 0; b < 8; b++)
#pragma unroll
            for (int c = 0; c < 4; c++) acc[a][b][c] = 0.f;

#define F2_LOAD(kt, slot) do { \
    uint32_t s_ = sb + (slot) * F2_STAGE; \
    const char* as_ = aSrc + (kt) * 64; \
    CP16(s_ + aDst, as_);  CP16(s_ + aDst + 16, as_ + 16); \
    CP16(s_ + bdst0, bBase + (size_t)((kt) * 32 + bk0) * 2048 + bc0); \
    CP16(s_ + bdst1, bBase + (size_t)((kt) * 32 + bk1) * 2048 + bc1); \
    CP_COMMIT(); \
} while (0)

    F2_LOAD(0, 0);
    F2_LOAD(1, 1);

    uint32_t l16 = (uint32_t)(lane & 15), lh = (uint32_t)(lane >> 4) * 16;

    const int NIT = FF / 32;
#pragma unroll 1
    for (int kt = 0; kt < NIT; kt++) {
        if (kt == NIT - 1) { CP_WAIT(0); } else { CP_WAIT(1); }
        __syncthreads();
        if (kt + 2 < NIT) F2_LOAD(kt + 2, (kt + 2) % 3);

        uint32_t stg = sb + (kt % 3) * F2_STAGE;
#pragma unroll
        for (int ks = 0; ks < 2; ks++) {
            uint32_t a_fr[2][4];
#pragma unroll
            for (int mt = 0; mt < 2; mt++) {
                uint32_t aa = stg + (wm * 32 + mt * 16 + l16) * 80 + ks * 32 + lh;
                LDSM4(a_fr[mt][0], a_fr[mt][1], a_fr[mt][2], a_fr[mt][3], aa);
            }
#pragma unroll
            for (int nt = 0; nt < 4; nt++) {
                uint32_t ba = stg + F2_BOFF + (ks * 16 + l16) * 272 +
                              (wn * 64 + nt * 16) * 2 + lh;
                uint32_t b0, b1, b2, b3;
                LDSM4T(b0, b1, b2, b3, ba);
#pragma unroll
                for (int mt = 0; mt < 2; mt++) {
                    MMA_F16(acc[mt][nt*2],   a_fr[mt], b0, b1);
                    MMA_F16(acc[mt][nt*2+1], a_fr[mt], b2, b3);
                }
            }
        }
    }

#pragma unroll
    for (int mt = 0; mt < 2; mt++) {
        int r0 = m0 + wm * 32 + mt * 16 + ly;
#pragma unroll
        for (int nt = 0; nt < 8; nt++) {
            int c = n0 + wn * 64 + nt * 8 + 2 * lx;
            float* A = acc[mt][nt];
            *(float2*)(g_y + (size_t)r0 * DD + c)       = make_float2(A[0], A[1]);
            *(float2*)(g_y + (size_t)(r0 + 8) * DD + c) = make_float2(A[2], A[3]);
        }
    }
}

// ---------------- combine ----------------
__global__ void combine_kernel(float* __restrict__ out) {
    int t = blockIdx.x;
    int a0 = g_assign_pos[2*t];
    int a1 = g_assign_pos[2*t+1];
    const float4* y0 = (const float4*)(g_y + (size_t)a0 * DD);
    const float4* y1 = (const float4*)(g_y + (size_t)a1 * DD);
    float4* o = (float4*)(out + (size_t)t * DD);
    int j = threadIdx.x;
    float4 v0 = y0[j], v1 = y1[j];
    o[j] = make_float4(v0.x + v1.x, v0.y + v1.y, v0.z + v1.z, v0.w + v1.w);
}

// ---------------- launch ----------------
extern "C" void kernel_launch(void* const* d_in, const int* in_sizes, int n_in,
                              void* d_out, int out_size) {
    const float* x  = (const float*)d_in[0];
    const float* wr = (const float*)d_in[1];
    const float* wg = (const float*)d_in[2];
    const float* wu = (const float*)d_in[3];
    const float* wd = (const float*)d_in[4];
    float* out = (float*)d_out;

    cudaFuncSetAttribute(ff1_tc, cudaFuncAttributeMaxDynamicSharedMemorySize, 3 * F1_STAGE);
    cudaFuncSetAttribute(ff2_tc, cudaFuncAttributeMaxDynamicSharedMemorySize, 3 * F2_STAGE);

    init_kernel<<<(MAXA + 255) / 256, 256>>>();
    router_kernel<<<NTOK / 8, 256>>>(x, wr);
    offsets_kernel<<<1, 1>>>();
    scatter_kernel<<<(NASG + 255) / 256, 256>>>();

    __half* xh_p;  cudaGetSymbolAddress((void**)&xh_p,  g_xh);
    __half* wgh_p; cudaGetSymbolAddress((void**)&wgh_p, g_wgh);
    __half* wuh_p; cudaGetSymbolAddress((void**)&wuh_p, g_wuh);
    __half* wdh_p; cudaGetSymbolAddress((void**)&wdh_p, g_wdh);

    cvt_half<<<(NTOK*DD/4 + 255)/256, 256>>>(x,  xh_p,  NTOK*DD/4);
    cvt_half<<<(EE*DD*FF/4 + 255)/256, 256>>>(wg, wgh_p, EE*DD*FF/4);
    cvt_half<<<(EE*DD*FF/4 + 255)/256, 256>>>(wu, wuh_p, EE*DD*FF/4);
    cvt_half<<<(EE*FF*DD/4 + 255)/256, 256>>>(wd, wdh_p, EE*FF*DD/4);

    {
        dim3 g(FF / 64, MTILES);
        ff1_tc<<<g, 256, 3 * F1_STAGE>>>(xh_p, wgh_p, wuh_p);
    }
    {
        dim3 g(DD / 128, MTILES);
        ff2_tc<<<g, 256, 3 * F2_STAGE>>>(wdh_p);
    }
    combine_kernel<<<NTOK, 256>>>(out);
}

// round 6
// speedup vs baseline: 5.2556x; 1.0126x over previous
#include <cuda_runtime.h>
#include <cuda_fp16.h>
#include <math.h>
#include <stdint.h>

#define BB 4
#define TT 2048
#define DD 1024
#define EE 8
#define FF 1024
#define NTOK (BB*TT)           // 8192
#define NASG (NTOK*2)          // 16384
#define MAXA (NASG + EE*128)   // 17408
#define MTILES (MAXA/128)      // 136

// ---------------- scratch ----------------
__device__ int   g_counts[EE];
__device__ int   g_cursor[EE];
__device__ int   g_offsets[EE+1];
__device__ int   g_eidx[NASG];
__device__ float g_ew[NASG];
__device__ int   g_token_of[MAXA];
__device__ float g_weight_of[MAXA];
__device__ int   g_assign_pos[NASG];

__device__ __half g_xh [(size_t)NTOK*DD];
__device__ __half g_wgh[(size_t)EE*DD*FF];
__device__ __half g_wuh[(size_t)EE*DD*FF];
__device__ __half g_wdh[(size_t)EE*FF*DD];
__device__ __half g_h  [(size_t)MAXA*FF];
__device__ float  g_y  [(size_t)MAXA*DD];

// ---------------- PTX helpers ----------------
__device__ __forceinline__ uint32_t s2u(const void* p) {
    uint32_t a;
    asm("{ .reg .u64 t; cvta.to.shared.u64 t, %1; cvt.u32.u64 %0, t; }" : "=r"(a) : "l"(p));
    return a;
}
#define CP16(dst, src) \
    asm volatile("cp.async.cg.shared.global [%0], [%1], 16;" :: "r"(dst), "l"(src) : "memory")
#define CP_COMMIT() asm volatile("cp.async.commit_group;" ::: "memory")
#define CP_WAIT(N)  asm volatile("cp.async.wait_group %0;" :: "n"(N) : "memory")

#define LDSM4(r0, r1, r2, r3, a) \
    asm volatile("ldmatrix.sync.aligned.m8n8.x4.shared.b16 {%0,%1,%2,%3}, [%4];" \
        : "=r"(r0), "=r"(r1), "=r"(r2), "=r"(r3) : "r"(a))
#define LDSM4T(r0, r1, r2, r3, a) \
    asm volatile("ldmatrix.sync.aligned.m8n8.x4.trans.shared.b16 {%0,%1,%2,%3}, [%4];" \
        : "=r"(r0), "=r"(r1), "=r"(r2), "=r"(r3) : "r"(a))

// mma m16n8k16 fp16 in, fp32 acc
#define MMA_F16(d, a, b0, b1) \
    asm volatile("mma.sync.aligned.m16n8k16.row.col.f32.f16.f16.f32 " \
        "{%0,%1,%2,%3}, {%4,%5,%6,%7}, {%8,%9}, {%0,%1,%2,%3};" \
        : "+f"((d)[0]), "+f"((d)[1]), "+f"((d)[2]), "+f"((d)[3]) \
        : "r"((a)[0]), "r"((a)[1]), "r"((a)[2]), "r"((a)[3]), \
          "r"(b0), "r"(b1))

// ---------------- init ----------------
__global__ void init_kernel() {
    int i = blockIdx.x * blockDim.x + threadIdx.x;
    if (i < EE) { g_counts[i] = 0; g_cursor[i] = 0; }
    if (i < MAXA) { g_token_of[i] = -1; g_weight_of[i] = 0.f; }
}

// ---------------- fused fp32 -> fp16 convert (x, wg, wu, wd) ----------------
// 4 regions of exactly 2^21 float4 each.
__global__ void cvt_all(const float* __restrict__ x,  const float* __restrict__ wg,
                        const float* __restrict__ wu, const float* __restrict__ wd) {
    int idx = blockIdx.x * blockDim.x + threadIdx.x;   // 0 .. 4*2^21-1
    int region = idx >> 21;
    int off = idx & ((1 << 21) - 1);
    const float* src;
    __half* dst;
    switch (region) {
        case 0:  src = x;  dst = g_xh;  break;
        case 1:  src = wg; dst = g_wgh; break;
        case 2:  src = wu; dst = g_wuh; break;
        default: src = wd; dst = g_wdh; break;
    }
    float4 v = ((const float4*)src)[off];
    __half2 a = __floats2half2_rn(v.x, v.y);
    __half2 b = __floats2half2_rn(v.z, v.w);
    ((__half2*)dst)[2*off]   = a;
    ((__half2*)dst)[2*off+1] = b;
}

// ---------------- router ----------------
__global__ void router_kernel(const float* __restrict__ x,
                              const float* __restrict__ wr) {
    __shared__ float s_wr[DD * EE];
    int tid = threadIdx.x;
    for (int i = tid; i < DD * EE / 4; i += blockDim.x)
        ((float4*)s_wr)[i] = ((const float4*)wr)[i];
    __syncthreads();

    int warp = tid >> 5, lane = tid & 31;
    int t = blockIdx.x * 8 + warp;
    const float* xr = x + (size_t)t * DD;

    float acc[EE];
#pragma unroll
    for (int e = 0; e < EE; e++) acc[e] = 0.f;
#pragma unroll
    for (int i = 0; i < 8; i++) {
        int d0 = i * 128 + lane * 4;
        float4 xv = *(const float4*)(xr + d0);
        float xa[4] = { xv.x, xv.y, xv.z, xv.w };
#pragma unroll
        for (int j = 0; j < 4; j++) {
            const float4* wp = (const float4*)(s_wr + (size_t)(d0 + j) * EE);
            float4 w0 = wp[0], w1 = wp[1];
            acc[0] += xa[j] * w0.x;  acc[1] += xa[j] * w0.y;
            acc[2] += xa[j] * w0.z;  acc[3] += xa[j] * w0.w;
            acc[4] += xa[j] * w1.x;  acc[5] += xa[j] * w1.y;
            acc[6] += xa[j] * w1.z;  acc[7] += xa[j] * w1.w;
        }
    }
#pragma unroll
    for (int off = 16; off > 0; off >>= 1)
#pragma unroll
        for (int e = 0; e < EE; e++)
            acc[e] += __shfl_xor_sync(0xffffffffu, acc[e], off);

    if (lane == 0) {
        float m = acc[0];
#pragma unroll
        for (int e = 1; e < EE; e++) m = fmaxf(m, acc[e]);
        float p[EE], s = 0.f;
#pragma unroll
        for (int e = 0; e < EE; e++) { p[e] = expf(acc[e] - m); s += p[e]; }
        float inv = 1.f / s;
#pragma unroll
        for (int e = 0; e < EE; e++) p[e] *= inv;

        int be = 0; float b = p[0];
#pragma unroll
        for (int e = 1; e < EE; e++) if (p[e] > b) { b = p[e]; be = e; }
        int be2 = -1; float b2 = -1.f;
#pragma unroll
        for (int e = 0; e < EE; e++)
            if (e != be && p[e] > b2) { b2 = p[e]; be2 = e; }

        float w0 = 1.f / (1.f + expf(b2 - b));
        float w1 = 1.f - w0;

        g_eidx[2*t]   = be;   g_ew[2*t]   = w0;
        g_eidx[2*t+1] = be2;  g_ew[2*t+1] = w1;
        atomicAdd(&g_counts[be], 1);
        atomicAdd(&g_counts[be2], 1);
    }
}

__global__ void offsets_kernel() {
    int off = 0;
#pragma unroll
    for (int e = 0; e < EE; e++) {
        g_offsets[e] = off;
        off += (g_counts[e] + 127) & ~127;
    }
    g_offsets[EE] = off;
}

__global__ void scatter_kernel() {
    int i = blockIdx.x * blockDim.x + threadIdx.x;
    if (i >= NASG) return;
    int e = g_eidx[i];
    int pos = atomicAdd(&g_cursor[e], 1);
    int a = g_offsets[e] + pos;
    g_token_of[a] = i >> 1;
    g_weight_of[a] = g_ew[i];
    g_assign_pos[i] = a;
}

// ======================= ff1 : gate+up grouped GEMM (fp16 mma) ===============
// BM=128, BN=64 (two Bs), BK=32, 4 stages, 256 threads, warp tile 32x32.
// A stride 80 B (40 halves), B stride 144 B (72 halves). Stage = 19456 B.
#define F1_STAGE 19456
#define F1_BOFF  10240

__global__ void __launch_bounds__(256, 2)
ff1_tc(const __half* __restrict__ xh,
       const __half* __restrict__ wgh,
       const __half* __restrict__ wuh) {
    extern __shared__ char smem[];
    int m0 = blockIdx.y * 128;
    if (m0 >= g_offsets[EE]) return;
    int e = 0;
#pragma unroll
    for (int i = 0; i < EE; i++) if (m0 >= g_offsets[i+1]) e = i + 1;
    int n0 = blockIdx.x * 64;

    int tid = threadIdx.x, wid = tid >> 5, lane = tid & 31;
    int wm = wid & 3, wn = wid >> 2;
    int ly = lane >> 2, lx = lane & 3;
    uint32_t sb = s2u(smem);

    // loaders
    int ar = tid >> 1, ah = tid & 1;
    int tok = g_token_of[m0 + ar]; if (tok < 0) tok = 0;
    const char* aSrc = (const char*)(xh + (size_t)tok * DD) + ah * 32;
    uint32_t aDst = (uint32_t)(ar * 80 + ah * 32);
    const char* gBase = (const char*)(wgh + ((size_t)e << 20) + n0);
    const char* uBase = (const char*)(wuh + ((size_t)e << 20) + n0);
    int id0 = tid, id1 = tid + 256;
    int brow0 = id0 >> 3, bc0 = (id0 & 7) * 16;
    int brow1 = id1 >> 3, bc1 = (id1 & 7) * 16;
    int bmat0 = brow0 >> 5, bk0 = brow0 & 31;
    int bmat1 = brow1 >> 5, bk1 = brow1 & 31;
    const char* bsrc0 = (bmat0 ? uBase : gBase) + bc0;
    const char* bsrc1 = (bmat1 ? uBase : gBase) + bc1;
    uint32_t bdst0 = (uint32_t)(F1_BOFF + bmat0 * 4608 + bk0 * 144 + bc0);
    uint32_t bdst1 = (uint32_t)(F1_BOFF + bmat1 * 4608 + bk1 * 144 + bc1);

    float accG[2][4][4], accU[2][4][4];
#pragma unroll
    for (int a = 0; a < 2; a++)
#pragma unroll
        for (int b = 0; b < 4; b++)
#pragma unroll
            for (int c = 0; c < 4; c++) { accG[a][b][c] = 0.f; accU[a][b][c] = 0.f; }

#define F1_LOAD(kt, slot) do { \
    uint32_t s_ = sb + (slot) * F1_STAGE; \
    const char* as_ = aSrc + (kt) * 64; \
    CP16(s_ + aDst, as_);  CP16(s_ + aDst + 16, as_ + 16); \
    CP16(s_ + bdst0, bsrc0 + (size_t)((kt) * 32 + bk0) * 2048); \
    CP16(s_ + bdst1, bsrc1 + (size_t)((kt) * 32 + bk1) * 2048); \
    CP_COMMIT(); \
} while (0)

    F1_LOAD(0, 0);
    F1_LOAD(1, 1);
    F1_LOAD(2, 2);

    uint32_t l16 = (uint32_t)(lane & 15), lh = (uint32_t)(lane >> 4) * 16;

    const int NIT = DD / 32;
#pragma unroll 1
    for (int kt = 0; kt < NIT; kt++) {
        if (kt < NIT - 2)       { CP_WAIT(2); }
        else if (kt == NIT - 2) { CP_WAIT(1); }
        else                    { CP_WAIT(0); }
        __syncthreads();
        if (kt + 3 < NIT) F1_LOAD(kt + 3, (kt + 3) & 3);

        uint32_t stg = sb + (kt & 3) * F1_STAGE;
#pragma unroll
        for (int ks = 0; ks < 2; ks++) {
            uint32_t a_fr[2][4];
#pragma unroll
            for (int mt = 0; mt < 2; mt++) {
                uint32_t aa = stg + (wm * 32 + mt * 16 + l16) * 80 + ks * 32 + lh;
                LDSM4(a_fr[mt][0], a_fr[mt][1], a_fr[mt][2], a_fr[mt][3], aa);
            }
#pragma unroll
            for (int nt = 0; nt < 2; nt++) {
                uint32_t bg = stg + F1_BOFF + (ks * 16 + l16) * 144 +
                              (wn * 32 + nt * 16) * 2 + lh;
                uint32_t g0, g1, g2, g3, u0, u1, u2, u3;
                LDSM4T(g0, g1, g2, g3, bg);
                LDSM4T(u0, u1, u2, u3, bg + 4608);
#pragma unroll
                for (int mt = 0; mt < 2; mt++) {
                    MMA_F16(accG[mt][nt*2],   a_fr[mt], g0, g1);
                    MMA_F16(accG[mt][nt*2+1], a_fr[mt], g2, g3);
                    MMA_F16(accU[mt][nt*2],   a_fr[mt], u0, u1);
                    MMA_F16(accU[mt][nt*2+1], a_fr[mt], u2, u3);
                }
            }
        }
    }

    // epilogue: h = w * silu(g) * u -> fp16
#pragma unroll
    for (int mt = 0; mt < 2; mt++) {
        int r0 = m0 + wm * 32 + mt * 16 + ly;
        float w0 = g_weight_of[r0], w1 = g_weight_of[r0 + 8];
#pragma unroll
        for (int nt = 0; nt < 4; nt++) {
            int c = n0 + wn * 32 + nt * 8 + 2 * lx;
            float* G = accG[mt][nt];
            float* U = accU[mt][nt];
            float h0 = w0 * (G[0] / (1.f + __expf(-G[0]))) * U[0];
            float h1 = w0 * (G[1] / (1.f + __expf(-G[1]))) * U[1];
            float h2 = w1 * (G[2] / (1.f + __expf(-G[2]))) * U[2];
            float h3 = w1 * (G[3] / (1.f + __expf(-G[3]))) * U[3];
            *(__half2*)(g_h + (size_t)r0 * FF + c)       = __floats2half2_rn(h0, h1);
            *(__half2*)(g_h + (size_t)(r0 + 8) * FF + c) = __floats2half2_rn(h2, h3);
        }
    }
}

// ======================= ff2 : down grouped GEMM (fp16 mma) ==================
// BM=128, BN=128, BK=32, 4 stages, warp tile 32x64.
// A stride 80 B, B stride 272 B. Stage = 10240 + 8704 = 18944 B.
#define F2_STAGE 18944
#define F2_BOFF  10240

__global__ void __launch_bounds__(256, 2)
ff2_tc(const __half* __restrict__ wdh) {
    extern __shared__ char smem[];
    int m0 = blockIdx.y * 128;
    if (m0 >= g_offsets[EE]) return;
    int e = 0;
#pragma unroll
    for (int i = 0; i < EE; i++) if (m0 >= g_offsets[i+1]) e = i + 1;
    int n0 = blockIdx.x * 128;

    int tid = threadIdx.x, wid = tid >> 5, lane = tid & 31;
    int wm = wid & 3, wn = wid >> 2;
    int ly = lane >> 2, lx = lane & 3;
    uint32_t sb = s2u(smem);

    int ar = tid >> 1, ah = tid & 1;
    const char* aSrc = (const char*)(g_h + (size_t)(m0 + ar) * FF) + ah * 32;
    uint32_t aDst = (uint32_t)(ar * 80 + ah * 32);
    const char* bBase = (const char*)(wdh + ((size_t)e << 20) + n0);
    int id0 = tid, id1 = tid + 256;
    int bk0 = id0 >> 4, bc0 = (id0 & 15) * 16;
    int bk1 = id1 >> 4, bc1 = (id1 & 15) * 16;
    uint32_t bdst0 = (uint32_t)(F2_BOFF + bk0 * 272 + bc0);
    uint32_t bdst1 = (uint32_t)(F2_BOFF + bk1 * 272 + bc1);

    float acc[2][8][4];
#pragma unroll
    for (int a = 0; a < 2; a++)
#pragma unroll
        for (int b = 0; b < 8; b++)
#pragma unroll
            for (int c = 0; c < 4; c++) acc[a][b][c] = 0.f;

#define F2_LOAD(kt, slot) do { \
    uint32_t s_ = sb + (slot) * F2_STAGE; \
    const char* as_ = aSrc + (kt) * 64; \
    CP16(s_ + aDst, as_);  CP16(s_ + aDst + 16, as_ + 16); \
    CP16(s_ + bdst0, bBase + (size_t)((kt) * 32 + bk0) * 2048 + bc0); \
    CP16(s_ + bdst1, bBase + (size_t)((kt) * 32 + bk1) * 2048 + bc1); \
    CP_COMMIT(); \
} while (0)

    F2_LOAD(0, 0);
    F2_LOAD(1, 1);
    F2_LOAD(2, 2);

    uint32_t l16 = (uint32_t)(lane & 15), lh = (uint32_t)(lane >> 4) * 16;

    const int NIT = FF / 32;
#pragma unroll 1
    for (int kt = 0; kt < NIT; kt++) {
        if (kt < NIT - 2)       { CP_WAIT(2); }
        else if (kt == NIT - 2) { CP_WAIT(1); }
        else                    { CP_WAIT(0); }
        __syncthreads();
        if (kt + 3 < NIT) F2_LOAD(kt + 3, (kt + 3) & 3);

        uint32_t stg = sb + (kt & 3) * F2_STAGE;
#pragma unroll
        for (int ks = 0; ks < 2; ks++) {
            uint32_t a_fr[2][4];
#pragma unroll
            for (int mt = 0; mt < 2; mt++) {
                uint32_t aa = stg + (wm * 32 + mt * 16 + l16) * 80 + ks * 32 + lh;
                LDSM4(a_fr[mt][0], a_fr[mt][1], a_fr[mt][2], a_fr[mt][3], aa);
            }
#pragma unroll
            for (int nt = 0; nt < 4; nt++) {
                uint32_t ba = stg + F2_BOFF + (ks * 16 + l16) * 272 +
                              (wn * 64 + nt * 16) * 2 + lh;
                uint32_t b0, b1, b2, b3;
                LDSM4T(b0, b1, b2, b3, ba);
#pragma unroll
                for (int mt = 0; mt < 2; mt++) {
                    MMA_F16(acc[mt][nt*2],   a_fr[mt], b0, b1);
                    MMA_F16(acc[mt][nt*2+1], a_fr[mt], b2, b3);
                }
            }
        }
    }

#pragma unroll
    for (int mt = 0; mt < 2; mt++) {
        int r0 = m0 + wm * 32 + mt * 16 + ly;
#pragma unroll
        for (int nt = 0; nt < 8; nt++) {
            int c = n0 + wn * 64 + nt * 8 + 2 * lx;
            float* A = acc[mt][nt];
            *(float2*)(g_y + (size_t)r0 * DD + c)       = make_float2(A[0], A[1]);
            *(float2*)(g_y + (size_t)(r0 + 8) * DD + c) = make_float2(A[2], A[3]);
        }
    }
}

// ---------------- combine ----------------
__global__ void combine_kernel(float* __restrict__ out) {
    int t = blockIdx.x;
    int a0 = g_assign_pos[2*t];
    int a1 = g_assign_pos[2*t+1];
    const float4* y0 = (const float4*)(g_y + (size_t)a0 * DD);
    const float4* y1 = (const float4*)(g_y + (size_t)a1 * DD);
    float4* o = (float4*)(out + (size_t)t * DD);
    int j = threadIdx.x;
    float4 v0 = y0[j], v1 = y1[j];
    o[j] = make_float4(v0.x + v1.x, v0.y + v1.y, v0.z + v1.z, v0.w + v1.w);
}

// ---------------- launch ----------------
extern "C" void kernel_launch(void* const* d_in, const int* in_sizes, int n_in,
                              void* d_out, int out_size) {
    const float* x  = (const float*)d_in[0];
    const float* wr = (const float*)d_in[1];
    const float* wg = (const float*)d_in[2];
    const float* wu = (const float*)d_in[3];
    const float* wd = (const float*)d_in[4];
    float* out = (float*)d_out;

    cudaFuncSetAttribute(ff1_tc, cudaFuncAttributeMaxDynamicSharedMemorySize, 4 * F1_STAGE);
    cudaFuncSetAttribute(ff2_tc, cudaFuncAttributeMaxDynamicSharedMemorySize, 4 * F2_STAGE);

    init_kernel<<<(MAXA + 255) / 256, 256>>>();
    router_kernel<<<NTOK / 8, 256>>>(x, wr);
    offsets_kernel<<<1, 1>>>();
    scatter_kernel<<<(NASG + 255) / 256, 256>>>();
    cvt_all<<<(4 * (1 << 21)) / 256, 256>>>(x, wg, wu, wd);

    __half* xh_p;  cudaGetSymbolAddress((void**)&xh_p,  g_xh);
    __half* wgh_p; cudaGetSymbolAddress((void**)&wgh_p, g_wgh);
    __half* wuh_p; cudaGetSymbolAddress((void**)&wuh_p, g_wuh);
    __half* wdh_p; cudaGetSymbolAddress((void**)&wdh_p, g_wdh);

    {
        dim3 g(FF / 64, MTILES);
        ff1_tc<<<g, 256, 4 * F1_STAGE>>>(xh_p, wgh_p, wuh_p);
    }
    {
        dim3 g(DD / 128, MTILES);
        ff2_tc<<<g, 256, 4 * F2_STAGE>>>(wdh_p);
    }
    combine_kernel<<<NTOK, 256>>>(out);
}

// round 7
// speedup vs baseline: 5.2779x; 1.0043x over previous
#include <cuda_runtime.h>
#include <cuda_fp16.h>
#include <math.h>
#include <stdint.h>

#define BB 4
#define TT 2048
#define DD 1024
#define EE 8
#define FF 1024
#define NTOK (BB*TT)           // 8192
#define NASG (NTOK*2)          // 16384
#define MAXA (NASG + EE*128)   // 17408
#define MTILES (MAXA/128)      // 136

// ---------------- scratch ----------------
__device__ int   g_counts[EE];
__device__ int   g_cursor[EE];
__device__ int   g_offsets[EE+1];
__device__ int   g_eidx[NASG];
__device__ float g_ew[NASG];
__device__ int   g_token_of[MAXA];
__device__ float g_weight_of[MAXA];

__device__ __half g_xh [(size_t)NTOK*DD];
__device__ __half g_wgh[(size_t)EE*DD*FF];
__device__ __half g_wuh[(size_t)EE*DD*FF];
__device__ __half g_wdh[(size_t)EE*FF*DD];
__device__ __half g_h  [(size_t)MAXA*FF];

// ---------------- PTX helpers ----------------
__device__ __forceinline__ uint32_t s2u(const void* p) {
    uint32_t a;
    asm("{ .reg .u64 t; cvta.to.shared.u64 t, %1; cvt.u32.u64 %0, t; }" : "=r"(a) : "l"(p));
    return a;
}
#define CP16(dst, src) \
    asm volatile("cp.async.cg.shared.global [%0], [%1], 16;" :: "r"(dst), "l"(src) : "memory")
#define CP_COMMIT() asm volatile("cp.async.commit_group;" ::: "memory")
#define CP_WAIT(N)  asm volatile("cp.async.wait_group %0;" :: "n"(N) : "memory")

#define LDSM4(r0, r1, r2, r3, a) \
    asm volatile("ldmatrix.sync.aligned.m8n8.x4.shared.b16 {%0,%1,%2,%3}, [%4];" \
        : "=r"(r0), "=r"(r1), "=r"(r2), "=r"(r3) : "r"(a))
#define LDSM4T(r0, r1, r2, r3, a) \
    asm volatile("ldmatrix.sync.aligned.m8n8.x4.trans.shared.b16 {%0,%1,%2,%3}, [%4];" \
        : "=r"(r0), "=r"(r1), "=r"(r2), "=r"(r3) : "r"(a))

// mma m16n8k16 fp16 in, fp32 acc
#define MMA_F16(d, a, b0, b1) \
    asm volatile("mma.sync.aligned.m16n8k16.row.col.f32.f16.f16.f32 " \
        "{%0,%1,%2,%3}, {%4,%5,%6,%7}, {%8,%9}, {%0,%1,%2,%3};" \
        : "+f"((d)[0]), "+f"((d)[1]), "+f"((d)[2]), "+f"((d)[3]) \
        : "r"((a)[0]), "r"((a)[1]), "r"((a)[2]), "r"((a)[3]), \
          "r"(b0), "r"(b1))

// ---------------- init: clear counters + zero output ----------------
__global__ void init_kernel(float* __restrict__ out) {
    int i = blockIdx.x * blockDim.x + threadIdx.x;
    if (i < EE) { g_counts[i] = 0; g_cursor[i] = 0; }
    if (i < MAXA) { g_token_of[i] = -1; g_weight_of[i] = 0.f; }
    if (i < NTOK * DD / 4)
        ((float4*)out)[i] = make_float4(0.f, 0.f, 0.f, 0.f);
}

// ---------------- fused fp32 -> fp16 convert (wg, wu, wd) ----------------
__global__ void cvt_w(const float* __restrict__ wg,
                      const float* __restrict__ wu, const float* __restrict__ wd) {
    int idx = blockIdx.x * blockDim.x + threadIdx.x;   // 0 .. 3*2^21-1
    int region = idx >> 21;
    int off = idx & ((1 << 21) - 1);
    const float* src;
    __half* dst;
    switch (region) {
        case 0:  src = wg; dst = g_wgh; break;
        case 1:  src = wu; dst = g_wuh; break;
        default: src = wd; dst = g_wdh; break;
    }
    float4 v = ((const float4*)src)[off];
    __half2 a = __floats2half2_rn(v.x, v.y);
    __half2 b = __floats2half2_rn(v.z, v.w);
    ((__half2*)dst)[2*off]   = a;
    ((__half2*)dst)[2*off+1] = b;
}

// ---------------- router (also emits fp16 x) ----------------
__global__ void router_kernel(const float* __restrict__ x,
                              const float* __restrict__ wr) {
    __shared__ float s_wr[DD * EE];
    int tid = threadIdx.x;
    for (int i = tid; i < DD * EE / 4; i += blockDim.x)
        ((float4*)s_wr)[i] = ((const float4*)wr)[i];
    __syncthreads();

    int warp = tid >> 5, lane = tid & 31;
    int t = blockIdx.x * 8 + warp;
    const float* xr = x + (size_t)t * DD;

    float acc[EE];
#pragma unroll
    for (int e = 0; e < EE; e++) acc[e] = 0.f;
#pragma unroll
    for (int i = 0; i < 8; i++) {
        int d0 = i * 128 + lane * 4;
        float4 xv = *(const float4*)(xr + d0);
        // write fp16 copy of x
        __half2 p0 = __floats2half2_rn(xv.x, xv.y);
        __half2 p1 = __floats2half2_rn(xv.z, xv.w);
        uint2 pk = make_uint2(*(uint32_t*)&p0, *(uint32_t*)&p1);
        *(uint2*)(g_xh + (size_t)t * DD + d0) = pk;

        float xa[4] = { xv.x, xv.y, xv.z, xv.w };
#pragma unroll
        for (int j = 0; j < 4; j++) {
            const float4* wp = (const float4*)(s_wr + (size_t)(d0 + j) * EE);
            float4 w0 = wp[0], w1 = wp[1];
            acc[0] += xa[j] * w0.x;  acc[1] += xa[j] * w0.y;
            acc[2] += xa[j] * w0.z;  acc[3] += xa[j] * w0.w;
            acc[4] += xa[j] * w1.x;  acc[5] += xa[j] * w1.y;
            acc[6] += xa[j] * w1.z;  acc[7] += xa[j] * w1.w;
        }
    }
#pragma unroll
    for (int off = 16; off > 0; off >>= 1)
#pragma unroll
        for (int e = 0; e < EE; e++)
            acc[e] += __shfl_xor_sync(0xffffffffu, acc[e], off);

    if (lane == 0) {
        float m = acc[0];
#pragma unroll
        for (int e = 1; e < EE; e++) m = fmaxf(m, acc[e]);
        float p[EE], s = 0.f;
#pragma unroll
        for (int e = 0; e < EE; e++) { p[e] = expf(acc[e] - m); s += p[e]; }
        float inv = 1.f / s;
#pragma unroll
        for (int e = 0; e < EE; e++) p[e] *= inv;

        int be = 0; float b = p[0];
#pragma unroll
        for (int e = 1; e < EE; e++) if (p[e] > b) { b = p[e]; be = e; }
        int be2 = -1; float b2 = -1.f;
#pragma unroll
        for (int e = 0; e < EE; e++)
            if (e != be && p[e] > b2) { b2 = p[e]; be2 = e; }

        float w0 = 1.f / (1.f + expf(b2 - b));
        float w1 = 1.f - w0;

        g_eidx[2*t]   = be;   g_ew[2*t]   = w0;
        g_eidx[2*t+1] = be2;  g_ew[2*t+1] = w1;
        atomicAdd(&g_counts[be], 1);
        atomicAdd(&g_counts[be2], 1);
    }
}

__global__ void offsets_kernel() {
    int off = 0;
#pragma unroll
    for (int e = 0; e < EE; e++) {
        g_offsets[e] = off;
        off += (g_counts[e] + 127) & ~127;
    }
    g_offsets[EE] = off;
}

__global__ void scatter_kernel() {
    int i = blockIdx.x * blockDim.x + threadIdx.x;
    if (i >= NASG) return;
    int e = g_eidx[i];
    int pos = atomicAdd(&g_cursor[e], 1);
    int a = g_offsets[e] + pos;
    g_token_of[a] = i >> 1;
    g_weight_of[a] = g_ew[i];
}

// ======================= ff1 : gate+up grouped GEMM (fp16 mma) ===============
// BM=128, BN=64 (two Bs), BK=32, 4 stages, 256 threads, warp tile 32x32.
#define F1_STAGE 19456
#define F1_BOFF  10240

__global__ void __launch_bounds__(256, 2)
ff1_tc(const __half* __restrict__ xh,
       const __half* __restrict__ wgh,
       const __half* __restrict__ wuh) {
    extern __shared__ char smem[];
    int m0 = blockIdx.y * 128;
    if (m0 >= g_offsets[EE]) return;
    int e = 0;
#pragma unroll
    for (int i = 0; i < EE; i++) if (m0 >= g_offsets[i+1]) e = i + 1;
    int n0 = blockIdx.x * 64;

    int tid = threadIdx.x, wid = tid >> 5, lane = tid & 31;
    int wm = wid & 3, wn = wid >> 2;
    int ly = lane >> 2, lx = lane & 3;
    uint32_t sb = s2u(smem);

    int ar = tid >> 1, ah = tid & 1;
    int tok = g_token_of[m0 + ar]; if (tok < 0) tok = 0;
    const char* aSrc = (const char*)(xh + (size_t)tok * DD) + ah * 32;
    uint32_t aDst = (uint32_t)(ar * 80 + ah * 32);
    const char* gBase = (const char*)(wgh + ((size_t)e << 20) + n0);
    const char* uBase = (const char*)(wuh + ((size_t)e << 20) + n0);
    int id0 = tid, id1 = tid + 256;
    int brow0 = id0 >> 3, bc0 = (id0 & 7) * 16;
    int brow1 = id1 >> 3, bc1 = (id1 & 7) * 16;
    int bmat0 = brow0 >> 5, bk0 = brow0 & 31;
    int bmat1 = brow1 >> 5, bk1 = brow1 & 31;
    const char* bsrc0 = (bmat0 ? uBase : gBase) + bc0;
    const char* bsrc1 = (bmat1 ? uBase : gBase) + bc1;
    uint32_t bdst0 = (uint32_t)(F1_BOFF + bmat0 * 4608 + bk0 * 144 + bc0);
    uint32_t bdst1 = (uint32_t)(F1_BOFF + bmat1 * 4608 + bk1 * 144 + bc1);

    float accG[2][4][4], accU[2][4][4];
#pragma unroll
    for (int a = 0; a < 2; a++)
#pragma unroll
        for (int b = 0; b < 4; b++)
#pragma unroll
            for (int c = 0; c < 4; c++) { accG[a][b][c] = 0.f; accU[a][b][c] = 0.f; }

#define F1_LOAD(kt, slot) do { \
    uint32_t s_ = sb + (slot) * F1_STAGE; \
    const char* as_ = aSrc + (kt) * 64; \
    CP16(s_ + aDst, as_);  CP16(s_ + aDst + 16, as_ + 16); \
    CP16(s_ + bdst0, bsrc0 + (size_t)((kt) * 32 + bk0) * 2048); \
    CP16(s_ + bdst1, bsrc1 + (size_t)((kt) * 32 + bk1) * 2048); \
    CP_COMMIT(); \
} while (0)

    F1_LOAD(0, 0);
    F1_LOAD(1, 1);
    F1_LOAD(2, 2);

    uint32_t l16 = (uint32_t)(lane & 15), lh = (uint32_t)(lane >> 4) * 16;

    const int NIT = DD / 32;
#pragma unroll 1
    for (int kt = 0; kt < NIT; kt++) {
        if (kt < NIT - 2)       { CP_WAIT(2); }
        else if (kt == NIT - 2) { CP_WAIT(1); }
        else                    { CP_WAIT(0); }
        __syncthreads();
        if (kt + 3 < NIT) F1_LOAD(kt + 3, (kt + 3) & 3);

        uint32_t stg = sb + (kt & 3) * F1_STAGE;
#pragma unroll
        for (int ks = 0; ks < 2; ks++) {
            uint32_t a_fr[2][4];
#pragma unroll
            for (int mt = 0; mt < 2; mt++) {
                uint32_t aa = stg + (wm * 32 + mt * 16 + l16) * 80 + ks * 32 + lh;
                LDSM4(a_fr[mt][0], a_fr[mt][1], a_fr[mt][2], a_fr[mt][3], aa);
            }
#pragma unroll
            for (int nt = 0; nt < 2; nt++) {
                uint32_t bg = stg + F1_BOFF + (ks * 16 + l16) * 144 +
                              (wn * 32 + nt * 16) * 2 + lh;
                uint32_t g0, g1, g2, g3, u0, u1, u2, u3;
                LDSM4T(g0, g1, g2, g3, bg);
                LDSM4T(u0, u1, u2, u3, bg + 4608);
#pragma unroll
                for (int mt = 0; mt < 2; mt++) {
                    MMA_F16(accG[mt][nt*2],   a_fr[mt], g0, g1);
                    MMA_F16(accG[mt][nt*2+1], a_fr[mt], g2, g3);
                    MMA_F16(accU[mt][nt*2],   a_fr[mt], u0, u1);
                    MMA_F16(accU[mt][nt*2+1], a_fr[mt], u2, u3);
                }
            }
        }
    }

    // epilogue: h = w * silu(g) * u -> fp16
#pragma unroll
    for (int mt = 0; mt < 2; mt++) {
        int r0 = m0 + wm * 32 + mt * 16 + ly;
        float w0 = g_weight_of[r0], w1 = g_weight_of[r0 + 8];
#pragma unroll
        for (int nt = 0; nt < 4; nt++) {
            int c = n0 + wn * 32 + nt * 8 + 2 * lx;
            float* G = accG[mt][nt];
            float* U = accU[mt][nt];
            float h0 = w0 * (G[0] / (1.f + __expf(-G[0]))) * U[0];
            float h1 = w0 * (G[1] / (1.f + __expf(-G[1]))) * U[1];
            float h2 = w1 * (G[2] / (1.f + __expf(-G[2]))) * U[2];
            float h3 = w1 * (G[3] / (1.f + __expf(-G[3]))) * U[3];
            *(__half2*)(g_h + (size_t)r0 * FF + c)       = __floats2half2_rn(h0, h1);
            *(__half2*)(g_h + (size_t)(r0 + 8) * FF + c) = __floats2half2_rn(h2, h3);
        }
    }
}

// ======================= ff2 : down grouped GEMM (fp16 mma) ==================
// BM=128, BN=128, BK=32, 4 stages, warp tile 32x64. RED epilogue into out.
#define F2_STAGE 18944
#define F2_BOFF  10240

__global__ void __launch_bounds__(256, 2)
ff2_tc(const __half* __restrict__ wdh, float* __restrict__ out) {
    extern __shared__ char smem[];
    int m0 = blockIdx.y * 128;
    if (m0 >= g_offsets[EE]) return;
    int e = 0;
#pragma unroll
    for (int i = 0; i < EE; i++) if (m0 >= g_offsets[i+1]) e = i + 1;
    int n0 = blockIdx.x * 128;

    int tid = threadIdx.x, wid = tid >> 5, lane = tid & 31;
    int wm = wid & 3, wn = wid >> 2;
    int ly = lane >> 2, lx = lane & 3;
    uint32_t sb = s2u(smem);

    int ar = tid >> 1, ah = tid & 1;
    const char* aSrc = (const char*)(g_h + (size_t)(m0 + ar) * FF) + ah * 32;
    uint32_t aDst = (uint32_t)(ar * 80 + ah * 32);
    const char* bBase = (const char*)(wdh + ((size_t)e << 20) + n0);
    int id0 = tid, id1 = tid + 256;
    int bk0 = id0 >> 4, bc0 = (id0 & 15) * 16;
    int bk1 = id1 >> 4, bc1 = (id1 & 15) * 16;
    uint32_t bdst0 = (uint32_t)(F2_BOFF + bk0 * 272 + bc0);
    uint32_t bdst1 = (uint32_t)(F2_BOFF + bk1 * 272 + bc1);

    float acc[2][8][4];
#pragma unroll
    for (int a = 0; a < 2; a++)
#pragma unroll
        for (int b = 0; b < 8; b++)
#pragma unroll
            for (int c = 0; c < 4; c++) acc[a][b][c] = 0.f;

#define F2_LOAD(kt, slot) do { \
    uint32_t s_ = sb + (slot) * F2_STAGE; \
    const char* as_ = aSrc + (kt) * 64; \
    CP16(s_ + aDst, as_);  CP16(s_ + aDst + 16, as_ + 16); \
    CP16(s_ + bdst0, bBase + (size_t)((kt) * 32 + bk0) * 2048 + bc0); \
    CP16(s_ + bdst1, bBase + (size_t)((kt) * 32 + bk1) * 2048 + bc1); \
    CP_COMMIT(); \
} while (0)

    F2_LOAD(0, 0);
    F2_LOAD(1, 1);
    F2_LOAD(2, 2);

    uint32_t l16 = (uint32_t)(lane & 15), lh = (uint32_t)(lane >> 4) * 16;

    const int NIT = FF / 32;
#pragma unroll 1
    for (int kt = 0; kt < NIT; kt++) {
        if (kt < NIT - 2)       { CP_WAIT(2); }
        else if (kt == NIT - 2) { CP_WAIT(1); }
        else                    { CP_WAIT(0); }
        __syncthreads();
        if (kt + 3 < NIT) F2_LOAD(kt + 3, (kt + 3) & 3);

        uint32_t stg = sb + (kt & 3) * F2_STAGE;
#pragma unroll
        for (int ks = 0; ks < 2; ks++) {
            uint32_t a_fr[2][4];
#pragma unroll
            for (int mt = 0; mt < 2; mt++) {
                uint32_t aa = stg + (wm * 32 + mt * 16 + l16) * 80 + ks * 32 + lh;
                LDSM4(a_fr[mt][0], a_fr[mt][1], a_fr[mt][2], a_fr[mt][3], aa);
            }
#pragma unroll
            for (int nt = 0; nt < 4; nt++) {
                uint32_t ba = stg + F2_BOFF + (ks * 16 + l16) * 272 +
                              (wn * 64 + nt * 16) * 2 + lh;
                uint32_t b0, b1, b2, b3;
                LDSM4T(b0, b1, b2, b3, ba);
#pragma unroll
                for (int mt = 0; mt < 2; mt++) {
                    MMA_F16(acc[mt][nt*2],   a_fr[mt], b0, b1);
                    MMA_F16(acc[mt][nt*2+1], a_fr[mt], b2, b3);
                }
            }
        }
    }

    // RED epilogue: out[token] += y (2 contributions per element, commutative)
#pragma unroll
    for (int mt = 0; mt < 2; mt++) {
        int r0 = m0 + wm * 32 + mt * 16 + ly;
        int t0 = g_token_of[r0], t1 = g_token_of[r0 + 8];
        float* o0 = out + (size_t)(t0 < 0 ? 0 : t0) * DD;
        float* o1 = out + (size_t)(t1 < 0 ? 0 : t1) * DD;
#pragma unroll
        for (int nt = 0; nt < 8; nt++) {
            int c = n0 + wn * 64 + nt * 8 + 2 * lx;
            float* A = acc[mt][nt];
            if (t0 >= 0) { atomicAdd(o0 + c, A[0]); atomicAdd(o0 + c + 1, A[1]); }
            if (t1 >= 0) { atomicAdd(o1 + c, A[2]); atomicAdd(o1 + c + 1, A[3]); }
        }
    }
}

// ---------------- launch ----------------
extern "C" void kernel_launch(void* const* d_in, const int* in_sizes, int n_in,
                              void* d_out, int out_size) {
    const float* x  = (const float*)d_in[0];
    const float* wr = (const float*)d_in[1];
    const float* wg = (const float*)d_in[2];
    const float* wu = (const float*)d_in[3];
    const float* wd = (const float*)d_in[4];
    float* out = (float*)d_out;

    cudaFuncSetAttribute(ff1_tc, cudaFuncAttributeMaxDynamicSharedMemorySize, 4 * F1_STAGE);
    cudaFuncSetAttribute(ff2_tc, cudaFuncAttributeMaxDynamicSharedMemorySize, 4 * F2_STAGE);

    init_kernel<<<(NTOK * DD / 4 + 255) / 256, 256>>>(out);
    router_kernel<<<NTOK / 8, 256>>>(x, wr);
    offsets_kernel<<<1, 1>>>();
    scatter_kernel<<<(NASG + 255) / 256, 256>>>();
    cvt_w<<<(3 * (1 << 21)) / 256, 256>>>(wg, wu, wd);

    __half* xh_p;  cudaGetSymbolAddress((void**)&xh_p,  g_xh);
    __half* wgh_p; cudaGetSymbolAddress((void**)&wgh_p, g_wgh);
    __half* wuh_p; cudaGetSymbolAddress((void**)&wuh_p, g_wuh);
    __half* wdh_p; cudaGetSymbolAddress((void**)&wdh_p, g_wdh);

    {
        dim3 g(FF / 64, MTILES);
        ff1_tc<<<g, 256, 4 * F1_STAGE>>>(xh_p, wgh_p, wuh_p);
    }
    {
        dim3 g(DD / 128, MTILES);
        ff2_tc<<<g, 256, 4 * F2_STAGE>>>(wdh_p, out);
    }
}

// round 8
// speedup vs baseline: 5.3008x; 1.0043x over previous
#include <cuda_runtime.h>
#include <cuda_fp16.h>
#include <math.h>
#include <stdint.h>

#define BB 4
#define TT 2048
#define DD 1024
#define EE 8
#define FF 1024
#define NTOK (BB*TT)           // 8192
#define NASG (NTOK*2)          // 16384
#define MAXA (NASG + EE*128)   // 17408
#define MTILES (MAXA/128)      // 136

// ---------------- scratch ----------------
__device__ int   g_counts[EE];
__device__ int   g_cursor[EE];
__device__ int   g_offsets[EE+1];
__device__ int   g_eidx[NASG];
__device__ float g_ew[NASG];
__device__ int   g_token_of[MAXA];
__device__ float g_weight_of[MAXA];
__device__ int   g_flag;

__device__ __half g_xh [(size_t)NTOK*DD];
__device__ __half g_wgh[(size_t)EE*DD*FF];
__device__ __half g_wuh[(size_t)EE*DD*FF];
__device__ __half g_wdh[(size_t)EE*FF*DD];
__device__ __half g_h  [(size_t)MAXA*FF];

// ---------------- PTX helpers ----------------
__device__ __forceinline__ uint32_t s2u(const void* p) {
    uint32_t a;
    asm("{ .reg .u64 t; cvta.to.shared.u64 t, %1; cvt.u32.u64 %0, t; }" : "=r"(a) : "l"(p));
    return a;
}
#define CP16(dst, src) \
    asm volatile("cp.async.cg.shared.global [%0], [%1], 16;" :: "r"(dst), "l"(src) : "memory")
#define CP_COMMIT() asm volatile("cp.async.commit_group;" ::: "memory")
#define CP_WAIT(N)  asm volatile("cp.async.wait_group %0;" :: "n"(N) : "memory")

#define LDSM4(r0, r1, r2, r3, a) \
    asm volatile("ldmatrix.sync.aligned.m8n8.x4.shared.b16 {%0,%1,%2,%3}, [%4];" \
        : "=r"(r0), "=r"(r1), "=r"(r2), "=r"(r3) : "r"(a))
#define LDSM4T(r0, r1, r2, r3, a) \
    asm volatile("ldmatrix.sync.aligned.m8n8.x4.trans.shared.b16 {%0,%1,%2,%3}, [%4];" \
        : "=r"(r0), "=r"(r1), "=r"(r2), "=r"(r3) : "r"(a))

// mma m16n8k16 fp16 in, fp32 acc
#define MMA_F16(d, a, b0, b1) \
    asm volatile("mma.sync.aligned.m16n8k16.row.col.f32.f16.f16.f32 " \
        "{%0,%1,%2,%3}, {%4,%5,%6,%7}, {%8,%9}, {%0,%1,%2,%3};" \
        : "+f"((d)[0]), "+f"((d)[1]), "+f"((d)[2]), "+f"((d)[3]) \
        : "r"((a)[0]), "r"((a)[1]), "r"((a)[2]), "r"((a)[3]), \
          "r"(b0), "r"(b1))

// ---------------- prep: zero out + counters + weight fp16 convert ----------
// idx < 2M           : zero out (float4)
// idx in [2M, 8M)    : convert weights, region (idx-2M)>>21
__global__ void prep_kernel(float* __restrict__ out,
                            const float* __restrict__ wg,
                            const float* __restrict__ wu,
                            const float* __restrict__ wd) {
    int idx = blockIdx.x * blockDim.x + threadIdx.x;     // 0 .. 8M-1
    if (idx < EE) { g_counts[idx] = 0; g_cursor[idx] = 0; }
    if (idx == 0) g_flag = 0;
    if (idx < MAXA) { g_token_of[idx] = -1; g_weight_of[idx] = 0.f; }

    const int OUT4 = NTOK * DD / 4;                      // 2M
    if (idx < OUT4) {
        ((float4*)out)[idx] = make_float4(0.f, 0.f, 0.f, 0.f);
    } else {
        int j = idx - OUT4;                              // 0 .. 6M-1
        int region = j >> 21;
        int off = j & ((1 << 21) - 1);
        const float* src;
        __half* dst;
        switch (region) {
            case 0:  src = wg; dst = g_wgh; break;
            case 1:  src = wu; dst = g_wuh; break;
            default: src = wd; dst = g_wdh; break;
        }
        float4 v = ((const float4*)src)[off];
        __half2 a = __floats2half2_rn(v.x, v.y);
        __half2 b = __floats2half2_rn(v.z, v.w);
        ((__half2*)dst)[2*off]   = a;
        ((__half2*)dst)[2*off+1] = b;
    }
}

// ---------------- router (also emits fp16 x) ----------------
__global__ void router_kernel(const float* __restrict__ x,
                              const float* __restrict__ wr) {
    __shared__ float s_wr[DD * EE];
    int tid = threadIdx.x;
    for (int i = tid; i < DD * EE / 4; i += blockDim.x)
        ((float4*)s_wr)[i] = ((const float4*)wr)[i];
    __syncthreads();

    int warp = tid >> 5, lane = tid & 31;
    int t = blockIdx.x * 8 + warp;
    const float* xr = x + (size_t)t * DD;

    float acc[EE];
#pragma unroll
    for (int e = 0; e < EE; e++) acc[e] = 0.f;
#pragma unroll
    for (int i = 0; i < 8; i++) {
        int d0 = i * 128 + lane * 4;
        float4 xv = *(const float4*)(xr + d0);
        __half2 p0 = __floats2half2_rn(xv.x, xv.y);
        __half2 p1 = __floats2half2_rn(xv.z, xv.w);
        uint2 pk = make_uint2(*(uint32_t*)&p0, *(uint32_t*)&p1);
        *(uint2*)(g_xh + (size_t)t * DD + d0) = pk;

        float xa[4] = { xv.x, xv.y, xv.z, xv.w };
#pragma unroll
        for (int j = 0; j < 4; j++) {
            const float4* wp = (const float4*)(s_wr + (size_t)(d0 + j) * EE);
            float4 w0 = wp[0], w1 = wp[1];
            acc[0] += xa[j] * w0.x;  acc[1] += xa[j] * w0.y;
            acc[2] += xa[j] * w0.z;  acc[3] += xa[j] * w0.w;
            acc[4] += xa[j] * w1.x;  acc[5] += xa[j] * w1.y;
            acc[6] += xa[j] * w1.z;  acc[7] += xa[j] * w1.w;
        }
    }
#pragma unroll
    for (int off = 16; off > 0; off >>= 1)
#pragma unroll
        for (int e = 0; e < EE; e++)
            acc[e] += __shfl_xor_sync(0xffffffffu, acc[e], off);

    if (lane == 0) {
        float m = acc[0];
#pragma unroll
        for (int e = 1; e < EE; e++) m = fmaxf(m, acc[e]);
        float p[EE], s = 0.f;
#pragma unroll
        for (int e = 0; e < EE; e++) { p[e] = expf(acc[e] - m); s += p[e]; }
        float inv = 1.f / s;
#pragma unroll
        for (int e = 0; e < EE; e++) p[e] *= inv;

        int be = 0; float b = p[0];
#pragma unroll
        for (int e = 1; e < EE; e++) if (p[e] > b) { b = p[e]; be = e; }
        int be2 = -1; float b2 = -1.f;
#pragma unroll
        for (int e = 0; e < EE; e++)
            if (e != be && p[e] > b2) { b2 = p[e]; be2 = e; }

        float w0 = 1.f / (1.f + expf(b2 - b));
        float w1 = 1.f - w0;

        g_eidx[2*t]   = be;   g_ew[2*t]   = w0;
        g_eidx[2*t+1] = be2;  g_ew[2*t+1] = w1;
        atomicAdd(&g_counts[be], 1);
        atomicAdd(&g_counts[be2], 1);
    }
}

// ---------------- offsets + scatter fused (64 blocks, all resident) ---------
__global__ void offsets_scatter_kernel() {
    if (blockIdx.x == 0 && threadIdx.x == 0) {
        int off = 0;
#pragma unroll
        for (int e = 0; e < EE; e++) {
            g_offsets[e] = off;
            off += (g_counts[e] + 127) & ~127;
        }
        g_offsets[EE] = off;
        __threadfence();
        atomicExch(&g_flag, 1);
    }
    if (threadIdx.x == 0) {
        while (atomicAdd(&g_flag, 0) == 0) __nanosleep(64);
    }
    __syncthreads();

    int i = blockIdx.x * blockDim.x + threadIdx.x;
    if (i >= NASG) return;
    int e = g_eidx[i];
    int pos = atomicAdd(&g_cursor[e], 1);
    int a = g_offsets[e] + pos;
    g_token_of[a] = i >> 1;
    g_weight_of[a] = g_ew[i];
}

// ======================= ff1 : gate+up grouped GEMM (fp16 mma) ===============
#define F1_STAGE 19456
#define F1_BOFF  10240

__global__ void __launch_bounds__(256, 2)
ff1_tc(const __half* __restrict__ xh,
       const __half* __restrict__ wgh,
       const __half* __restrict__ wuh) {
    extern __shared__ char smem[];
    int m0 = blockIdx.y * 128;
    if (m0 >= g_offsets[EE]) return;
    int e = 0;
#pragma unroll
    for (int i = 0; i < EE; i++) if (m0 >= g_offsets[i+1]) e = i + 1;
    int n0 = blockIdx.x * 64;

    int tid = threadIdx.x, wid = tid >> 5, lane = tid & 31;
    int wm = wid & 3, wn = wid >> 2;
    int ly = lane >> 2, lx = lane & 3;
    uint32_t sb = s2u(smem);

    int ar = tid >> 1, ah = tid & 1;
    int tok = g_token_of[m0 + ar]; if (tok < 0) tok = 0;
    const char* aSrc = (const char*)(xh + (size_t)tok * DD) + ah * 32;
    uint32_t aDst = (uint32_t)(ar * 80 + ah * 32);
    const char* gBase = (const char*)(wgh + ((size_t)e << 20) + n0);
    const char* uBase = (const char*)(wuh + ((size_t)e << 20) + n0);
    int id0 = tid, id1 = tid + 256;
    int brow0 = id0 >> 3, bc0 = (id0 & 7) * 16;
    int brow1 = id1 >> 3, bc1 = (id1 & 7) * 16;
    int bmat0 = brow0 >> 5, bk0 = brow0 & 31;
    int bmat1 = brow1 >> 5, bk1 = brow1 & 31;
    const char* bsrc0 = (bmat0 ? uBase : gBase) + bc0;
    const char* bsrc1 = (bmat1 ? uBase : gBase) + bc1;
    uint32_t bdst0 = (uint32_t)(F1_BOFF + bmat0 * 4608 + bk0 * 144 + bc0);
    uint32_t bdst1 = (uint32_t)(F1_BOFF + bmat1 * 4608 + bk1 * 144 + bc1);

    float accG[2][4][4], accU[2][4][4];
#pragma unroll
    for (int a = 0; a < 2; a++)
#pragma unroll
        for (int b = 0; b < 4; b++)
#pragma unroll
            for (int c = 0; c < 4; c++) { accG[a][b][c] = 0.f; accU[a][b][c] = 0.f; }

#define F1_LOAD(kt, slot) do { \
    uint32_t s_ = sb + (slot) * F1_STAGE; \
    const char* as_ = aSrc + (kt) * 64; \
    CP16(s_ + aDst, as_);  CP16(s_ + aDst + 16, as_ + 16); \
    CP16(s_ + bdst0, bsrc0 + (size_t)((kt) * 32 + bk0) * 2048); \
    CP16(s_ + bdst1, bsrc1 + (size_t)((kt) * 32 + bk1) * 2048); \
    CP_COMMIT(); \
} while (0)

    F1_LOAD(0, 0);
    F1_LOAD(1, 1);
    F1_LOAD(2, 2);

    uint32_t l16 = (uint32_t)(lane & 15), lh = (uint32_t)(lane >> 4) * 16;

    const int NIT = DD / 32;
#pragma unroll 1
    for (int kt = 0; kt < NIT; kt++) {
        if (kt < NIT - 2)       { CP_WAIT(2); }
        else if (kt == NIT - 2) { CP_WAIT(1); }
        else                    { CP_WAIT(0); }
        __syncthreads();
        if (kt + 3 < NIT) F1_LOAD(kt + 3, (kt + 3) & 3);

        uint32_t stg = sb + (kt & 3) * F1_STAGE;
#pragma unroll
        for (int ks = 0; ks < 2; ks++) {
            uint32_t a_fr[2][4];
#pragma unroll
            for (int mt = 0; mt < 2; mt++) {
                uint32_t aa = stg + (wm * 32 + mt * 16 + l16) * 80 + ks * 32 + lh;
                LDSM4(a_fr[mt][0], a_fr[mt][1], a_fr[mt][2], a_fr[mt][3], aa);
            }
#pragma unroll
            for (int nt = 0; nt < 2; nt++) {
                uint32_t bg = stg + F1_BOFF + (ks * 16 + l16) * 144 +
                              (wn * 32 + nt * 16) * 2 + lh;
                uint32_t g0, g1, g2, g3, u0, u1, u2, u3;
                LDSM4T(g0, g1, g2, g3, bg);
                LDSM4T(u0, u1, u2, u3, bg + 4608);
#pragma unroll
                for (int mt = 0; mt < 2; mt++) {
                    MMA_F16(accG[mt][nt*2],   a_fr[mt], g0, g1);
                    MMA_F16(accG[mt][nt*2+1], a_fr[mt], g2, g3);
                    MMA_F16(accU[mt][nt*2],   a_fr[mt], u0, u1);
                    MMA_F16(accU[mt][nt*2+1], a_fr[mt], u2, u3);
                }
            }
        }
    }

#pragma unroll
    for (int mt = 0; mt < 2; mt++) {
        int r0 = m0 + wm * 32 + mt * 16 + ly;
        float w0 = g_weight_of[r0], w1 = g_weight_of[r0 + 8];
#pragma unroll
        for (int nt = 0; nt < 4; nt++) {
            int c = n0 + wn * 32 + nt * 8 + 2 * lx;
            float* G = accG[mt][nt];
            float* U = accU[mt][nt];
            float h0 = w0 * (G[0] / (1.f + __expf(-G[0]))) * U[0];
            float h1 = w0 * (G[1] / (1.f + __expf(-G[1]))) * U[1];
            float h2 = w1 * (G[2] / (1.f + __expf(-G[2]))) * U[2];
            float h3 = w1 * (G[3] / (1.f + __expf(-G[3]))) * U[3];
            *(__half2*)(g_h + (size_t)r0 * FF + c)       = __floats2half2_rn(h0, h1);
            *(__half2*)(g_h + (size_t)(r0 + 8) * FF + c) = __floats2half2_rn(h2, h3);
        }
    }
}

// ======================= ff2 : down grouped GEMM (fp16 mma) ==================
#define F2_STAGE 18944
#define F2_BOFF  10240

__global__ void __launch_bounds__(256, 2)
ff2_tc(const __half* __restrict__ wdh, float* __restrict__ out) {
    extern __shared__ char smem[];
    int m0 = blockIdx.y * 128;
    if (m0 >= g_offsets[EE]) return;
    int e = 0;
#pragma unroll
    for (int i = 0; i < EE; i++) if (m0 >= g_offsets[i+1]) e = i + 1;
    int n0 = blockIdx.x * 128;

    int tid = threadIdx.x, wid = tid >> 5, lane = tid & 31;
    int wm = wid & 3, wn = wid >> 2;
    int ly = lane >> 2, lx = lane & 3;
    uint32_t sb = s2u(smem);

    int ar = tid >> 1, ah = tid & 1;
    const char* aSrc = (const char*)(g_h + (size_t)(m0 + ar) * FF) + ah * 32;
    uint32_t aDst = (uint32_t)(ar * 80 + ah * 32);
    const char* bBase = (const char*)(wdh + ((size_t)e << 20) + n0);
    int id0 = tid, id1 = tid + 256;
    int bk0 = id0 >> 4, bc0 = (id0 & 15) * 16;
    int bk1 = id1 >> 4, bc1 = (id1 & 15) * 16;
    uint32_t bdst0 = (uint32_t)(F2_BOFF + bk0 * 272 + bc0);
    uint32_t bdst1 = (uint32_t)(F2_BOFF + bk1 * 272 + bc1);

    float acc[2][8][4];
#pragma unroll
    for (int a = 0; a < 2; a++)
#pragma unroll
        for (int b = 0; b < 8; b++)
#pragma unroll
            for (int c = 0; c < 4; c++) acc[a][b][c] = 0.f;

#define F2_LOAD(kt, slot) do { \
    uint32_t s_ = sb + (slot) * F2_STAGE; \
    const char* as_ = aSrc + (kt) * 64; \
    CP16(s_ + aDst, as_);  CP16(s_ + aDst + 16, as_ + 16); \
    CP16(s_ + bdst0, bBase + (size_t)((kt) * 32 + bk0) * 2048 + bc0); \
    CP16(s_ + bdst1, bBase + (size_t)((kt) * 32 + bk1) * 2048 + bc1); \
    CP_COMMIT(); \
} while (0)

    F2_LOAD(0, 0);
    F2_LOAD(1, 1);
    F2_LOAD(2, 2);

    uint32_t l16 = (uint32_t)(lane & 15), lh = (uint32_t)(lane >> 4) * 16;

    const int NIT = FF / 32;
#pragma unroll 1
    for (int kt = 0; kt < NIT; kt++) {
        if (kt < NIT - 2)       { CP_WAIT(2); }
        else if (kt == NIT - 2) { CP_WAIT(1); }
        else                    { CP_WAIT(0); }
        __syncthreads();
        if (kt + 3 < NIT) F2_LOAD(kt + 3, (kt + 3) & 3);

        uint32_t stg = sb + (kt & 3) * F2_STAGE;
#pragma unroll
        for (int ks = 0; ks < 2; ks++) {
            uint32_t a_fr[2][4];
#pragma unroll
            for (int mt = 0; mt < 2; mt++) {
                uint32_t aa = stg + (wm * 32 + mt * 16 + l16) * 80 + ks * 32 + lh;
                LDSM4(a_fr[mt][0], a_fr[mt][1], a_fr[mt][2], a_fr[mt][3], aa);
            }
#pragma unroll
            for (int nt = 0; nt < 4; nt++) {
                uint32_t ba = stg + F2_BOFF + (ks * 16 + l16) * 272 +
                              (wn * 64 + nt * 16) * 2 + lh;
                uint32_t b0, b1, b2, b3;
                LDSM4T(b0, b1, b2, b3, ba);
#pragma unroll
                for (int mt = 0; mt < 2; mt++) {
                    MMA_F16(acc[mt][nt*2],   a_fr[mt], b0, b1);
                    MMA_F16(acc[mt][nt*2+1], a_fr[mt], b2, b3);
                }
            }
        }
    }

    // RED epilogue: out[token] += y
#pragma unroll
    for (int mt = 0; mt < 2; mt++) {
        int r0 = m0 + wm * 32 + mt * 16 + ly;
        int t0 = g_token_of[r0], t1 = g_token_of[r0 + 8];
        float* o0 = out + (size_t)(t0 < 0 ? 0 : t0) * DD;
        float* o1 = out + (size_t)(t1 < 0 ? 0 : t1) * DD;
#pragma unroll
        for (int nt = 0; nt < 8; nt++) {
            int c = n0 + wn * 64 + nt * 8 + 2 * lx;
            float* A = acc[mt][nt];
            if (t0 >= 0) { atomicAdd(o0 + c, A[0]); atomicAdd(o0 + c + 1, A[1]); }
            if (t1 >= 0) { atomicAdd(o1 + c, A[2]); atomicAdd(o1 + c + 1, A[3]); }
        }
    }
}

// ---------------- launch ----------------
extern "C" void kernel_launch(void* const* d_in, const int* in_sizes, int n_in,
                              void* d_out, int out_size) {
    const float* x  = (const float*)d_in[0];
    const float* wr = (const float*)d_in[1];
    const float* wg = (const float*)d_in[2];
    const float* wu = (const float*)d_in[3];
    const float* wd = (const float*)d_in[4];
    float* out = (float*)d_out;

    cudaFuncSetAttribute(ff1_tc, cudaFuncAttributeMaxDynamicSharedMemorySize, 4 * F1_STAGE);
    cudaFuncSetAttribute(ff2_tc, cudaFuncAttributeMaxDynamicSharedMemorySize, 4 * F2_STAGE);

    // total prep work: 2M (out zero) + 6M (weight cvt) float4 -> 8M threads
    prep_kernel<<<(8 * (1 << 20)) / 256, 256>>>(out, wg, wu, wd);
    router_kernel<<<NTOK / 8, 256>>>(x, wr);
    offsets_scatter_kernel<<<NASG / 256, 256>>>();

    __half* xh_p;  cudaGetSymbolAddress((void**)&xh_p,  g_xh);
    __half* wgh_p; cudaGetSymbolAddress((void**)&wgh_p, g_wgh);
    __half* wuh_p; cudaGetSymbolAddress((void**)&wuh_p, g_wuh);
    __half* wdh_p; cudaGetSymbolAddress((void**)&wdh_p, g_wdh);

    {
        dim3 g(FF / 64, MTILES);
        ff1_tc<<<g, 256, 4 * F1_STAGE>>>(xh_p, wgh_p, wuh_p);
    }
    {
        dim3 g(DD / 128, MTILES);
        ff2_tc<<<g, 256, 4 * F2_STAGE>>>(wdh_p, out);
    }
}